// round 3
// baseline (speedup 1.0000x reference)
#include <cuda_runtime.h>
#include <cstdint>
#include <math.h>

#define NNODES 50000
#define NEDGES 800000
#define FDIM   256
#define NCLS   40

// -------- scratch (device globals; referenced directly by kernels) --------
__device__ float g_bufA[(size_t)NNODES * FDIM];
__device__ float g_bufB[(size_t)NNODES * FDIM];
__device__ int   g_deg[NNODES];
__device__ int   g_off[NNODES];
__device__ int   g_rowptr[NNODES + 1];
__device__ int   g_col[NEDGES];
__device__ int   g_not64;   // 0 => edge_index is int64; nonzero => int32

// -------- dtype detection --------
__global__ void detect_reset_kernel() {
    if (threadIdx.x == 0 && blockIdx.x == 0) g_not64 = 0;
}

__global__ void detect_dtype_kernel(const void* __restrict__ ei) {
    int i = blockIdx.x * blockDim.x + threadIdx.x;
    if (i < 2 * NEDGES) {
        long long v = ((const long long*)ei)[i];
        if (v < 0 || v >= NNODES) atomicOr(&g_not64, 1);
    }
}

__device__ __forceinline__ int edge_at(const void* ei, int idx) {
    if (g_not64 == 0) return (int)((const long long*)ei)[idx];
    return ((const int*)ei)[idx];
}

// -------- CSR build --------
__global__ void zero2_kernel() {
    int i = blockIdx.x * blockDim.x + threadIdx.x;
    if (i < NNODES) { g_deg[i] = 0; g_off[i] = 0; }
}

__global__ void count_deg_kernel(const void* __restrict__ ei) {
    int e = blockIdx.x * blockDim.x + threadIdx.x;
    if (e < NEDGES) {
        int d = edge_at(ei, NEDGES + e);   // dst
        if ((unsigned)d < NNODES) atomicAdd(&g_deg[d], 1);
    }
}

// single-block exclusive scan: g_deg[N] -> g_rowptr[N+1]
__global__ void scan_kernel() {
    __shared__ int sums[1024];
    const int n = NNODES;
    int tid = threadIdx.x;
    int chunk = (n + 1023) / 1024;
    int start = tid * chunk;
    int s = 0;
    for (int i = 0; i < chunk; i++) {
        int idx = start + i;
        if (idx < n) s += g_deg[idx];
    }
    sums[tid] = s;
    __syncthreads();
    for (int off = 1; off < 1024; off <<= 1) {
        int v = 0;
        if (tid >= off) v = sums[tid - off];
        __syncthreads();
        if (tid >= off) sums[tid] += v;
        __syncthreads();
    }
    int base = sums[tid] - s;
    int run = base;
    for (int i = 0; i < chunk; i++) {
        int idx = start + i;
        if (idx < n) { g_rowptr[idx] = run; run += g_deg[idx]; }
    }
    if (tid == 0) g_rowptr[n] = sums[1023];
}

__global__ void fill_kernel(const void* __restrict__ ei) {
    int e = blockIdx.x * blockDim.x + threadIdx.x;
    if (e < NEDGES) {
        int s = edge_at(ei, e);
        int d = edge_at(ei, NEDGES + e);
        if ((unsigned)s < NNODES && (unsigned)d < NNODES) {
            int pos = g_rowptr[d] + atomicAdd(&g_off[d], 1);
            if ((unsigned)pos < NEDGES) g_col[pos] = s;
        }
    }
}

// -------- aggregation: g_bufA[v] = sum_{j in row v} in[col[j]] --------
__global__ void agg1_kernel(const float* __restrict__ in) {
    int v = blockIdx.x;
    int f = threadIdx.x;
    int s = g_rowptr[v];
    int e = g_rowptr[v + 1];
    float acc = 0.f;
    for (int j = s; j < e; j++) {
        int c = __ldg(&g_col[j]);
        acc += __ldg(&in[(size_t)c * FDIM + f]);
    }
    g_bufA[(size_t)v * FDIM + f] = acc;
}

__global__ void aggBA_kernel() {   // in = g_bufB, out = g_bufA
    int v = blockIdx.x;
    int f = threadIdx.x;
    int s = g_rowptr[v];
    int e = g_rowptr[v + 1];
    float acc = 0.f;
    for (int j = s; j < e; j++) {
        int c = __ldg(&g_col[j]);
        acc += g_bufB[(size_t)c * FDIM + f];
    }
    g_bufA[(size_t)v * FDIM + f] = acc;
}

// -------- fused SGEMM + bias + relu : g_bufB = relu(g_bufA @ W + b) --------
__global__ void gemm_bias_relu_kernel(const float* __restrict__ W, const float* __restrict__ bias,
                                      int M) {
    __shared__ __align__(16) float sA[16][64];
    __shared__ __align__(16) float sB[16][64];
    int m0 = blockIdx.x * 64;
    int n0 = blockIdx.y * 64;
    int tid = threadIdx.x;
    int ty = tid >> 4;
    int tx = tid & 15;
    int lr = tid >> 2;
    int lc = (tid & 3) * 4;
    int wr = tid >> 4;
    int wc = (tid & 15) * 4;

    float acc[4][4];
#pragma unroll
    for (int i = 0; i < 4; i++)
#pragma unroll
        for (int j = 0; j < 4; j++) acc[i][j] = 0.f;

    for (int k0 = 0; k0 < 256; k0 += 16) {
        float4 av = make_float4(0.f, 0.f, 0.f, 0.f);
        if (m0 + lr < M)
            av = *(const float4*)&g_bufA[(size_t)(m0 + lr) * 256 + k0 + lc];
        sA[lc + 0][lr] = av.x;
        sA[lc + 1][lr] = av.y;
        sA[lc + 2][lr] = av.z;
        sA[lc + 3][lr] = av.w;
        float4 wv = *(const float4*)&W[(size_t)(k0 + wr) * 256 + n0 + wc];
        *(float4*)&sB[wr][wc] = wv;
        __syncthreads();
#pragma unroll
        for (int kk = 0; kk < 16; kk++) {
            float4 ra = *(const float4*)&sA[kk][ty * 4];
            float4 rb = *(const float4*)&sB[kk][tx * 4];
            float a0 = ra.x, a1 = ra.y, a2 = ra.z, a3 = ra.w;
            float b0 = rb.x, b1 = rb.y, b2 = rb.z, b3 = rb.w;
            acc[0][0] += a0 * b0; acc[0][1] += a0 * b1; acc[0][2] += a0 * b2; acc[0][3] += a0 * b3;
            acc[1][0] += a1 * b0; acc[1][1] += a1 * b1; acc[1][2] += a1 * b2; acc[1][3] += a1 * b3;
            acc[2][0] += a2 * b0; acc[2][1] += a2 * b1; acc[2][2] += a2 * b2; acc[2][3] += a2 * b3;
            acc[3][0] += a3 * b0; acc[3][1] += a3 * b1; acc[3][2] += a3 * b2; acc[3][3] += a3 * b3;
        }
        __syncthreads();
    }

#pragma unroll
    for (int i = 0; i < 4; i++) {
        int row = m0 + ty * 4 + i;
        if (row < M) {
#pragma unroll
            for (int j = 0; j < 4; j++) {
                int c = n0 + tx * 4 + j;
                float v = acc[i][j] + bias[c];
                g_bufB[(size_t)row * 256 + c] = fmaxf(v, 0.f);
            }
        }
    }
}

// -------- output layer: logits = g_bufA @ W3 + b3, log_softmax; one warp/row --------
__global__ void out_logsoftmax_kernel(const float* __restrict__ W, const float* __restrict__ b,
                                      float* __restrict__ out, int M) {
    int warp = (blockIdx.x * blockDim.x + threadIdx.x) >> 5;
    int lane = threadIdx.x & 31;
    if (warp >= M) return;
    const float* a = &g_bufA[(size_t)warp * 256];
    bool act = lane < 20;
    int c0 = lane, c1 = lane + 20;
    float acc0 = 0.f, acc1 = 0.f;
    for (int k = 0; k < 256; k++) {
        float av = a[k];
        if (act) {
            acc0 += av * __ldg(&W[k * NCLS + c0]);
            acc1 += av * __ldg(&W[k * NCLS + c1]);
        }
    }
    float v0 = act ? acc0 + b[c0] : -INFINITY;
    float v1 = act ? acc1 + b[c1] : -INFINITY;
    float m = fmaxf(v0, v1);
#pragma unroll
    for (int o = 16; o > 0; o >>= 1) m = fmaxf(m, __shfl_xor_sync(0xFFFFFFFFu, m, o));
    float s = act ? (expf(v0 - m) + expf(v1 - m)) : 0.f;
#pragma unroll
    for (int o = 16; o > 0; o >>= 1) s += __shfl_xor_sync(0xFFFFFFFFu, s, o);
    float ls = logf(s);
    if (act) {
        out[(size_t)warp * NCLS + c0] = v0 - m - ls;
        out[(size_t)warp * NCLS + c1] = v1 - m - ls;
    }
}

__global__ void tail_kernel(float* out, int start, int total, float val) {
    int i = start + blockIdx.x * blockDim.x + threadIdx.x;
    if (i < total) out[i] = val;
}

extern "C" void kernel_launch(void* const* d_in, const int* in_sizes, int n_in,
                              void* d_out, int out_size) {
    const float* features = (const float*)d_in[0];
    const void*  ei       = d_in[1];
    // d_in[2] labels, d_in[3] mask: unused
    const float* W1 = (const float*)d_in[4];
    const float* b1 = (const float*)d_in[5];
    const float* W2 = (const float*)d_in[6];
    const float* b2 = (const float*)d_in[7];
    const float* W3 = (const float*)d_in[8];
    const float* b3 = (const float*)d_in[9];
    float* out = (float*)d_out;

    const int N = NNODES, E = NEDGES;

    // dtype detect (int64 vs int32 edge_index)
    detect_reset_kernel<<<1, 32>>>();
    detect_dtype_kernel<<<(2 * E + 255) / 256, 256>>>(ei);

    // CSR build (edges keyed by dst)
    zero2_kernel<<<(N + 255) / 256, 256>>>();
    count_deg_kernel<<<(E + 255) / 256, 256>>>(ei);
    scan_kernel<<<1, 1024>>>();
    fill_kernel<<<(E + 255) / 256, 256>>>(ei);

    dim3 ggrid((N + 63) / 64, 256 / 64);

    // layer 1
    agg1_kernel<<<N, 256>>>(features);
    gemm_bias_relu_kernel<<<ggrid, 256>>>(W1, b1, N);
    // layer 2
    aggBA_kernel<<<N, 256>>>();
    gemm_bias_relu_kernel<<<ggrid, 256>>>(W2, b2, N);
    // output
    aggBA_kernel<<<N, 256>>>();
    out_logsoftmax_kernel<<<(N * 32 + 255) / 256, 256>>>(W3, b3, out, N);

    // trailing elements (node_count = 3*N)
    int NC = N * NCLS;
    if (out_size > NC) {
        int extra = out_size - NC;
        tail_kernel<<<(extra + 255) / 256, 256>>>(out, NC, out_size, (float)(3 * N));
    }
}

// round 4
// speedup vs baseline: 1.3913x; 1.3913x over previous
#include <cuda_runtime.h>
#include <cstdint>
#include <math.h>

#define NNODES 50000
#define NEDGES 800000
#define FDIM   256
#define NCLS   40

// -------- scratch --------
__device__ float g_bufA[(size_t)NNODES * FDIM];
__device__ float g_bufB[(size_t)NNODES * FDIM];
__device__ float g_P[(size_t)NNODES * NCLS];
__device__ int   g_deg[NNODES];
__device__ int   g_off[NNODES];
__device__ int   g_rowptr[NNODES + 1];
__device__ int   g_col[NEDGES];
__device__ int   g_not64;

// -------- setup: zero counters + reset dtype flag --------
__global__ void setup_kernel() {
    int i = blockIdx.x * blockDim.x + threadIdx.x;
    if (i < NNODES) { g_deg[i] = 0; g_off[i] = 0; }
    if (i == 0) g_not64 = 0;
}

__global__ void detect_dtype_kernel(const void* __restrict__ ei) {
    int i = blockIdx.x * blockDim.x + threadIdx.x;
    if (i < 2 * NEDGES) {
        long long v = ((const long long*)ei)[i];
        if (v < 0 || v >= NNODES) atomicOr(&g_not64, 1);
    }
}

__device__ __forceinline__ int edge_at(const void* ei, int idx) {
    if (g_not64 == 0) return (int)((const long long*)ei)[idx];
    return ((const int*)ei)[idx];
}

__global__ void count_deg_kernel(const void* __restrict__ ei) {
    int e = blockIdx.x * blockDim.x + threadIdx.x;
    if (e < NEDGES) {
        int d = edge_at(ei, NEDGES + e);
        if ((unsigned)d < NNODES) atomicAdd(&g_deg[d], 1);
    }
}

__global__ void scan_kernel() {
    __shared__ int sums[1024];
    const int n = NNODES;
    int tid = threadIdx.x;
    int chunk = (n + 1023) / 1024;
    int start = tid * chunk;
    int s = 0;
    for (int i = 0; i < chunk; i++) {
        int idx = start + i;
        if (idx < n) s += g_deg[idx];
    }
    sums[tid] = s;
    __syncthreads();
    for (int off = 1; off < 1024; off <<= 1) {
        int v = 0;
        if (tid >= off) v = sums[tid - off];
        __syncthreads();
        if (tid >= off) sums[tid] += v;
        __syncthreads();
    }
    int base = sums[tid] - s;
    int run = base;
    for (int i = 0; i < chunk; i++) {
        int idx = start + i;
        if (idx < n) { g_rowptr[idx] = run; run += g_deg[idx]; }
    }
    if (tid == 0) g_rowptr[n] = sums[1023];
}

__global__ void fill_kernel(const void* __restrict__ ei) {
    int e = blockIdx.x * blockDim.x + threadIdx.x;
    if (e < NEDGES) {
        int s = edge_at(ei, e);
        int d = edge_at(ei, NEDGES + e);
        if ((unsigned)s < NNODES && (unsigned)d < NNODES) {
            int pos = g_rowptr[d] + atomicAdd(&g_off[d], 1);
            if ((unsigned)pos < NEDGES) g_col[pos] = s;
        }
    }
}

// -------- float4 aggregation: 4 nodes/block, 64 threads/node, 4 accumulators --------
__device__ __forceinline__ void agg_body(const float4* __restrict__ in, float4* __restrict__ out) {
    int t = blockIdx.x * blockDim.x + threadIdx.x;
    int v = t >> 6;
    int f = t & 63;
    if (v >= NNODES) return;
    int s = __ldg(&g_rowptr[v]);
    int e = __ldg(&g_rowptr[v + 1]);
    float4 a0 = make_float4(0.f, 0.f, 0.f, 0.f);
    float4 a1 = a0, a2 = a0, a3 = a0;
    int j = s;
    for (; j + 4 <= e; j += 4) {
        int c0 = __ldg(&g_col[j]);
        int c1 = __ldg(&g_col[j + 1]);
        int c2 = __ldg(&g_col[j + 2]);
        int c3 = __ldg(&g_col[j + 3]);
        float4 x0 = __ldg(&in[(size_t)c0 * 64 + f]);
        float4 x1 = __ldg(&in[(size_t)c1 * 64 + f]);
        float4 x2 = __ldg(&in[(size_t)c2 * 64 + f]);
        float4 x3 = __ldg(&in[(size_t)c3 * 64 + f]);
        a0.x += x0.x; a0.y += x0.y; a0.z += x0.z; a0.w += x0.w;
        a1.x += x1.x; a1.y += x1.y; a1.z += x1.z; a1.w += x1.w;
        a2.x += x2.x; a2.y += x2.y; a2.z += x2.z; a2.w += x2.w;
        a3.x += x3.x; a3.y += x3.y; a3.z += x3.z; a3.w += x3.w;
    }
    for (; j < e; j++) {
        int c = __ldg(&g_col[j]);
        float4 x = __ldg(&in[(size_t)c * 64 + f]);
        a0.x += x.x; a0.y += x.y; a0.z += x.z; a0.w += x.w;
    }
    float4 r;
    r.x = (a0.x + a1.x) + (a2.x + a3.x);
    r.y = (a0.y + a1.y) + (a2.y + a3.y);
    r.z = (a0.z + a1.z) + (a2.z + a3.z);
    r.w = (a0.w + a1.w) + (a2.w + a3.w);
    out[(size_t)v * 64 + f] = r;
}

__global__ void agg1_kernel(const float* __restrict__ in) {
    agg_body((const float4*)in, (float4*)g_bufA);
}
__global__ void aggBA_kernel() {
    agg_body((const float4*)g_bufB, (float4*)g_bufA);
}

// -------- 128x128 double-buffered SGEMM + bias + relu: g_bufB = relu(g_bufA@W + b) --------
__global__ void __launch_bounds__(256, 2)
gemm_bias_relu_kernel(const float* __restrict__ W, const float* __restrict__ bias, int M) {
    __shared__ __align__(16) float sA[2][8][128];
    __shared__ __align__(16) float sB[2][8][128];
    const int m0 = blockIdx.x * 128;
    const int n0 = blockIdx.y * 128;
    const int tid = threadIdx.x;
    const int tm = tid >> 4;          // 0..15
    const int tn = tid & 15;          // 0..15

    // loaders
    const int ar = tid >> 1;          // 0..127 row in A tile
    const int ak = (tid & 1) * 4;     // k offset
    const int br = tid >> 5;          // 0..7 k row in W tile
    const int bn = (tid & 31) * 4;    // n offset

    float acc[8][8];
#pragma unroll
    for (int i = 0; i < 8; i++)
#pragma unroll
        for (int j = 0; j < 8; j++) acc[i][j] = 0.f;

    float4 pa, pb;
    // prologue: tile 0
    pa = make_float4(0.f, 0.f, 0.f, 0.f);
    if (m0 + ar < M) pa = *(const float4*)&g_bufA[(size_t)(m0 + ar) * 256 + ak];
    pb = *(const float4*)&W[(size_t)br * 256 + n0 + bn];
    sA[0][ak + 0][ar] = pa.x;
    sA[0][ak + 1][ar] = pa.y;
    sA[0][ak + 2][ar] = pa.z;
    sA[0][ak + 3][ar] = pa.w;
    *(float4*)&sB[0][br][bn] = pb;

    int p = 0;
    for (int kt = 0; kt < 32; kt++) {
        __syncthreads();
        if (kt < 31) {
            int k0 = (kt + 1) * 8;
            pa = make_float4(0.f, 0.f, 0.f, 0.f);
            if (m0 + ar < M) pa = *(const float4*)&g_bufA[(size_t)(m0 + ar) * 256 + k0 + ak];
            pb = *(const float4*)&W[(size_t)(k0 + br) * 256 + n0 + bn];
        }
#pragma unroll
        for (int kk = 0; kk < 8; kk++) {
            float4 a0 = *(const float4*)&sA[p][kk][tm * 8];
            float4 a1 = *(const float4*)&sA[p][kk][tm * 8 + 4];
            float4 b0 = *(const float4*)&sB[p][kk][tn * 8];
            float4 b1 = *(const float4*)&sB[p][kk][tn * 8 + 4];
            float av[8] = {a0.x, a0.y, a0.z, a0.w, a1.x, a1.y, a1.z, a1.w};
            float bv[8] = {b0.x, b0.y, b0.z, b0.w, b1.x, b1.y, b1.z, b1.w};
#pragma unroll
            for (int i = 0; i < 8; i++)
#pragma unroll
                for (int j = 0; j < 8; j++) acc[i][j] += av[i] * bv[j];
        }
        if (kt < 31) {
            int q = p ^ 1;
            sA[q][ak + 0][ar] = pa.x;
            sA[q][ak + 1][ar] = pa.y;
            sA[q][ak + 2][ar] = pa.z;
            sA[q][ak + 3][ar] = pa.w;
            *(float4*)&sB[q][br][bn] = pb;
            p = q;
        }
    }

#pragma unroll
    for (int i = 0; i < 8; i++) {
        int row = m0 + tm * 8 + i;
        if (row < M) {
#pragma unroll
            for (int j = 0; j < 8; j += 4) {
                int c = n0 + tn * 8 + j;
                float4 v;
                v.x = fmaxf(acc[i][j + 0] + bias[c + 0], 0.f);
                v.y = fmaxf(acc[i][j + 1] + bias[c + 1], 0.f);
                v.z = fmaxf(acc[i][j + 2] + bias[c + 2], 0.f);
                v.w = fmaxf(acc[i][j + 3] + bias[c + 3], 0.f);
                *(float4*)&g_bufB[(size_t)row * 256 + c] = v;
            }
        }
    }
}

// -------- layer-3 projection (NO bias): g_P = g_bufB @ W3   [M,256]x[256,40] --------
__global__ void __launch_bounds__(256, 2)
gemm3_kernel(const float* __restrict__ W3, int M) {
    __shared__ float sW[256][40];          // 40 KB
    __shared__ __align__(16) float sA[64][128];  // 32 KB, [k][row]
    const int m0 = blockIdx.x * 128;
    const int tid = threadIdx.x;
    const int rt = tid >> 3;     // 0..31 -> rows rt*4..+3
    const int ct = tid & 7;      // 0..7  -> classes ct*5..+4

    // load W3 into smem: 256*40 floats = 10240 = 40 per thread
    for (int i = tid; i < 256 * 40; i += 256) sW[i / 40][i % 40] = __ldg(&W3[i]);

    float acc[4][5];
#pragma unroll
    for (int i = 0; i < 4; i++)
#pragma unroll
        for (int j = 0; j < 5; j++) acc[i][j] = 0.f;

    const int ar = tid >> 1;           // 0..127
    const int akb = (tid & 1) * 4;

    for (int k0 = 0; k0 < 256; k0 += 64) {
        __syncthreads();
        // load A chunk [64 k][128 rows] transposed
#pragma unroll
        for (int pass = 0; pass < 8; pass++) {
            int ak = akb + pass * 8;
            float4 av = make_float4(0.f, 0.f, 0.f, 0.f);
            if (m0 + ar < M) av = *(const float4*)&g_bufB[(size_t)(m0 + ar) * 256 + k0 + ak];
            sA[ak + 0][ar] = av.x;
            sA[ak + 1][ar] = av.y;
            sA[ak + 2][ar] = av.z;
            sA[ak + 3][ar] = av.w;
        }
        __syncthreads();
        for (int kk = 0; kk < 64; kk++) {
            float4 a4 = *(const float4*)&sA[kk][rt * 4];
            float a[4] = {a4.x, a4.y, a4.z, a4.w};
            const float* wrow = &sW[k0 + kk][ct * 5];
            float w0 = wrow[0], w1 = wrow[1], w2 = wrow[2], w3 = wrow[3], w4 = wrow[4];
#pragma unroll
            for (int i = 0; i < 4; i++) {
                acc[i][0] += a[i] * w0;
                acc[i][1] += a[i] * w1;
                acc[i][2] += a[i] * w2;
                acc[i][3] += a[i] * w3;
                acc[i][4] += a[i] * w4;
            }
        }
    }

#pragma unroll
    for (int i = 0; i < 4; i++) {
        int row = m0 + rt * 4 + i;
        if (row < M) {
#pragma unroll
            for (int j = 0; j < 5; j++)
                g_P[(size_t)row * NCLS + ct * 5 + j] = acc[i][j];
        }
    }
}

// -------- final: out[v] = log_softmax( sum_{nbr} P[nbr] + b3 ); warp per node --------
__global__ void aggout_kernel(const float* __restrict__ b3, float* __restrict__ out, int M) {
    int warp = (blockIdx.x * blockDim.x + threadIdx.x) >> 5;
    int lane = threadIdx.x & 31;
    if (warp >= M) return;
    int s = __ldg(&g_rowptr[warp]);
    int e = __ldg(&g_rowptr[warp + 1]);
    bool act = lane < 20;
    int c0 = lane, c1 = lane + 20;
    float acc0 = 0.f, acc1 = 0.f;
    for (int j = s; j < e; j++) {
        int c = __ldg(&g_col[j]);
        const float* pr = &g_P[(size_t)c * NCLS];
        if (act) {
            acc0 += pr[c0];
            acc1 += pr[c1];
        }
    }
    float v0 = act ? acc0 + __ldg(&b3[c0]) : -INFINITY;
    float v1 = act ? acc1 + __ldg(&b3[c1]) : -INFINITY;
    float m = fmaxf(v0, v1);
#pragma unroll
    for (int o = 16; o > 0; o >>= 1) m = fmaxf(m, __shfl_xor_sync(0xFFFFFFFFu, m, o));
    float ssum = act ? (expf(v0 - m) + expf(v1 - m)) : 0.f;
#pragma unroll
    for (int o = 16; o > 0; o >>= 1) ssum += __shfl_xor_sync(0xFFFFFFFFu, ssum, o);
    float ls = logf(ssum);
    if (act) {
        out[(size_t)warp * NCLS + c0] = v0 - m - ls;
        out[(size_t)warp * NCLS + c1] = v1 - m - ls;
    }
}

__global__ void tail_kernel(float* out, int start, int total, float val) {
    int i = start + blockIdx.x * blockDim.x + threadIdx.x;
    if (i < total) out[i] = val;
}

extern "C" void kernel_launch(void* const* d_in, const int* in_sizes, int n_in,
                              void* d_out, int out_size) {
    const float* features = (const float*)d_in[0];
    const void*  ei       = d_in[1];
    const float* W1 = (const float*)d_in[4];
    const float* b1 = (const float*)d_in[5];
    const float* W2 = (const float*)d_in[6];
    const float* b2 = (const float*)d_in[7];
    const float* W3 = (const float*)d_in[8];
    const float* b3 = (const float*)d_in[9];
    float* out = (float*)d_out;

    const int N = NNODES, E = NEDGES;

    setup_kernel<<<(N + 255) / 256, 256>>>();                 // 1
    detect_dtype_kernel<<<(2 * E + 255) / 256, 256>>>(ei);    // 2
    count_deg_kernel<<<(E + 255) / 256, 256>>>(ei);           // 3
    scan_kernel<<<1, 1024>>>();                               // 4
    fill_kernel<<<(E + 255) / 256, 256>>>(ei);                // 5

    dim3 ggrid((N + 127) / 128, 2);

    agg1_kernel<<<(N * 64 + 255) / 256, 256>>>(features);     // 6 (ncu target)
    gemm_bias_relu_kernel<<<ggrid, 256>>>(W1, b1, N);         // 7
    aggBA_kernel<<<(N * 64 + 255) / 256, 256>>>();            // 8
    gemm_bias_relu_kernel<<<ggrid, 256>>>(W2, b2, N);         // 9
    gemm3_kernel<<<(N + 127) / 128, 256>>>(W3, N);            // 10
    aggout_kernel<<<(N * 32 + 255) / 256, 256>>>(b3, out, N); // 11

    int NC = N * NCLS;
    if (out_size > NC) {
        int extra = out_size - NC;
        tail_kernel<<<(extra + 255) / 256, 256>>>(out, NC, out_size, (float)(3 * N));
    }
}

// round 5
// speedup vs baseline: 1.9054x; 1.3696x over previous
#include <cuda_runtime.h>
#include <cstdint>
#include <math.h>

#define NNODES 50000
#define NEDGES 800000
#define FDIM   256
#define NCLS   40
#define SCAN_BLOCKS ((NNODES + 1023) / 1024)

// -------- scratch --------
__device__ float g_bufA[(size_t)NNODES * FDIM];
__device__ float g_bufB[(size_t)NNODES * FDIM];
__device__ float g_P[(size_t)NNODES * NCLS];
__device__ int   g_deg[NNODES];
__device__ int   g_off[NNODES];
__device__ int   g_rowptr[NNODES + 1];
__device__ int   g_col[NEDGES];
__device__ int   g_bsum[SCAN_BLOCKS];
__device__ int   g_not64 = 0;   // monotone flag: set iff edge_index is int32

// -------- setup: zero counters + dtype detect (reads only first 2KB) --------
__global__ void setup_kernel(const void* __restrict__ ei) {
    int i = blockIdx.x * blockDim.x + threadIdx.x;
    if (i < NNODES) { g_deg[i] = 0; g_off[i] = 0; }
    if (blockIdx.x == 0 && threadIdx.x < 256) {
        // int64 little-endian values < 2^31 have zero high words at odd int32 idx
        const int* w = (const int*)ei;
        if (w[2 * threadIdx.x + 1] != 0) atomicOr(&g_not64, 1);
    }
}

__device__ __forceinline__ int edge_at(const void* ei, int idx) {
    if (g_not64 == 0) return (int)((const long long*)ei)[idx];
    return ((const int*)ei)[idx];
}

__global__ void count_deg_kernel(const void* __restrict__ ei) {
    int e = blockIdx.x * blockDim.x + threadIdx.x;
    if (e < NEDGES) {
        int d = edge_at(ei, NEDGES + e);
        if ((unsigned)d < NNODES) atomicAdd(&g_deg[d], 1);
    }
}

// -------- multiblock scan: deg -> rowptr --------
__global__ void scan_phaseA() {
    int i = blockIdx.x * 1024 + threadIdx.x;
    int v = (i < NNODES) ? g_deg[i] : 0;
    int s = v;
#pragma unroll
    for (int o = 16; o > 0; o >>= 1) s += __shfl_xor_sync(0xFFFFFFFFu, s, o);
    __shared__ int ws[32];
    int w = threadIdx.x >> 5, l = threadIdx.x & 31;
    if (l == 0) ws[w] = s;
    __syncthreads();
    if (w == 0) {
        int t = ws[l];
#pragma unroll
        for (int o = 16; o > 0; o >>= 1) t += __shfl_xor_sync(0xFFFFFFFFu, t, o);
        if (l == 0) g_bsum[blockIdx.x] = t;
    }
}

__global__ void scan_phaseC() {
    int i = blockIdx.x * 1024 + threadIdx.x;
    int v = (i < NNODES) ? g_deg[i] : 0;
    int w = threadIdx.x >> 5, l = threadIdx.x & 31;
    // warp inclusive scan
    int x = v;
#pragma unroll
    for (int o = 1; o < 32; o <<= 1) {
        int y = __shfl_up_sync(0xFFFFFFFFu, x, o);
        if (l >= o) x += y;
    }
    __shared__ int wtot[32];
    __shared__ int sboff;
    if (l == 31) wtot[w] = x;
    __syncthreads();
    if (w == 0) {
        // block offset: sum of previous blocks' sums
        int s = 0;
        for (int b = l; b < blockIdx.x; b += 32) s += g_bsum[b];
#pragma unroll
        for (int o = 16; o > 0; o >>= 1) s += __shfl_xor_sync(0xFFFFFFFFu, s, o);
        if (l == 0) sboff = s;
        // scan warp totals (inclusive)
        int t = wtot[l];
#pragma unroll
        for (int o = 1; o < 32; o <<= 1) {
            int y = __shfl_up_sync(0xFFFFFFFFu, t, o);
            if (l >= o) t += y;
        }
        wtot[l] = t;
    }
    __syncthreads();
    int woff = (w > 0) ? wtot[w - 1] : 0;
    int excl = sboff + woff + x - v;
    if (i < NNODES) g_rowptr[i] = excl;
    if (i == NNODES - 1) g_rowptr[NNODES] = excl + v;
}

__global__ void fill_kernel(const void* __restrict__ ei) {
    int e = blockIdx.x * blockDim.x + threadIdx.x;
    if (e < NEDGES) {
        int s = edge_at(ei, e);
        int d = edge_at(ei, NEDGES + e);
        if ((unsigned)s < NNODES && (unsigned)d < NNODES) {
            int pos = g_rowptr[d] + atomicAdd(&g_off[d], 1);
            if ((unsigned)pos < NEDGES) g_col[pos] = s;
        }
    }
}

// -------- float4 aggregation: 64 threads/node, 4-deep unroll --------
__device__ __forceinline__ void agg_body(const float4* __restrict__ in, float4* __restrict__ out) {
    int t = blockIdx.x * blockDim.x + threadIdx.x;
    int v = t >> 6;
    int f = t & 63;
    if (v >= NNODES) return;
    int s = __ldg(&g_rowptr[v]);
    int e = __ldg(&g_rowptr[v + 1]);
    float4 a0 = make_float4(0.f, 0.f, 0.f, 0.f);
    float4 a1 = a0, a2 = a0, a3 = a0;
    int j = s;
    for (; j + 4 <= e; j += 4) {
        int c0 = __ldg(&g_col[j]);
        int c1 = __ldg(&g_col[j + 1]);
        int c2 = __ldg(&g_col[j + 2]);
        int c3 = __ldg(&g_col[j + 3]);
        float4 x0 = __ldg(&in[(size_t)c0 * 64 + f]);
        float4 x1 = __ldg(&in[(size_t)c1 * 64 + f]);
        float4 x2 = __ldg(&in[(size_t)c2 * 64 + f]);
        float4 x3 = __ldg(&in[(size_t)c3 * 64 + f]);
        a0.x += x0.x; a0.y += x0.y; a0.z += x0.z; a0.w += x0.w;
        a1.x += x1.x; a1.y += x1.y; a1.z += x1.z; a1.w += x1.w;
        a2.x += x2.x; a2.y += x2.y; a2.z += x2.z; a2.w += x2.w;
        a3.x += x3.x; a3.y += x3.y; a3.z += x3.z; a3.w += x3.w;
    }
    for (; j < e; j++) {
        int c = __ldg(&g_col[j]);
        float4 x = __ldg(&in[(size_t)c * 64 + f]);
        a0.x += x.x; a0.y += x.y; a0.z += x.z; a0.w += x.w;
    }
    float4 r;
    r.x = (a0.x + a1.x) + (a2.x + a3.x);
    r.y = (a0.y + a1.y) + (a2.y + a3.y);
    r.z = (a0.z + a1.z) + (a2.z + a3.z);
    r.w = (a0.w + a1.w) + (a2.w + a3.w);
    out[(size_t)v * 64 + f] = r;
}

__global__ void agg1_kernel(const float* __restrict__ in) {
    agg_body((const float4*)in, (float4*)g_bufA);
}
__global__ void aggBA_kernel() {
    agg_body((const float4*)g_bufB, (float4*)g_bufA);
}

// -------- tf32 helpers --------
__device__ __forceinline__ unsigned f2tf32(float x) {
    unsigned y;
    asm("cvt.rna.tf32.f32 %0, %1;" : "=r"(y) : "f"(x));
    return y;
}

#define MMA_TF32(d, a, b) \
    asm volatile("mma.sync.aligned.m16n8k8.row.col.f32.tf32.tf32.f32 " \
        "{%0,%1,%2,%3}, {%4,%5,%6,%7}, {%8,%9}, {%0,%1,%2,%3};" \
        : "+f"(d[0]), "+f"(d[1]), "+f"(d[2]), "+f"(d[3]) \
        : "r"(a[0]), "r"(a[1]), "r"(a[2]), "r"(a[3]), "r"(b[0]), "r"(b[1]))

// -------- tf32-split GEMM + bias + relu: g_bufB = relu(g_bufA @ W + b) --------
// Block tile 128x128, 8 warps (2m x 4n), warp tile 64x32, k-step 16.
__global__ void __launch_bounds__(256)
gemm_tf32_kernel(const float* __restrict__ W, const float* __restrict__ bias, int M) {
    __shared__ unsigned sAh[128][20], sAl[128][20];    // rows: m, cols: k (0..15)
    __shared__ unsigned sBh[16][136], sBl[16][136];    // rows: k, cols: n (0..127)
    const int m0 = blockIdx.x * 128;
    const int n0 = blockIdx.y * 128;
    const int tid = threadIdx.x;
    const int warp = tid >> 5, lane = tid & 31;
    const int wm = warp >> 2, wn = warp & 3;    // 2 x 4 warps
    const int g = lane >> 2, l = lane & 3;

    // loader indices
    const int ar = tid >> 1;              // A row 0..127
    const int ac = (tid & 1) * 8;         // A k offset 0/8
    const int bkr = tid >> 4;             // B k row 0..15
    const int bnc = (tid & 15) * 8;       // B n offset 0..120

    float acc[4][4][4];
#pragma unroll
    for (int i = 0; i < 4; i++)
#pragma unroll
        for (int j = 0; j < 4; j++)
#pragma unroll
            for (int q = 0; q < 4; q++) acc[i][j][q] = 0.f;

    const bool aval = (m0 + ar) < M;
    const float* Arow = &g_bufA[(size_t)(m0 + ar) * 256];

    float4 fa0, fa1, fb0, fb1;
    // prefetch k-step 0
    fa0 = fa1 = make_float4(0.f, 0.f, 0.f, 0.f);
    if (aval) {
        fa0 = *(const float4*)&Arow[ac];
        fa1 = *(const float4*)&Arow[ac + 4];
    }
    fb0 = *(const float4*)&W[(size_t)bkr * 256 + n0 + bnc];
    fb1 = *(const float4*)&W[(size_t)bkr * 256 + n0 + bnc + 4];

#pragma unroll 1
    for (int kt = 0; kt < 16; kt++) {
        if (kt > 0) __syncthreads();
        // convert + store A
        {
            uint4 h, lo;
            h.x = f2tf32(fa0.x); h.y = f2tf32(fa0.y); h.z = f2tf32(fa0.z); h.w = f2tf32(fa0.w);
            lo.x = f2tf32(fa0.x - __uint_as_float(h.x));
            lo.y = f2tf32(fa0.y - __uint_as_float(h.y));
            lo.z = f2tf32(fa0.z - __uint_as_float(h.z));
            lo.w = f2tf32(fa0.w - __uint_as_float(h.w));
            *(uint4*)&sAh[ar][ac] = h;
            *(uint4*)&sAl[ar][ac] = lo;
            h.x = f2tf32(fa1.x); h.y = f2tf32(fa1.y); h.z = f2tf32(fa1.z); h.w = f2tf32(fa1.w);
            lo.x = f2tf32(fa1.x - __uint_as_float(h.x));
            lo.y = f2tf32(fa1.y - __uint_as_float(h.y));
            lo.z = f2tf32(fa1.z - __uint_as_float(h.z));
            lo.w = f2tf32(fa1.w - __uint_as_float(h.w));
            *(uint4*)&sAh[ar][ac + 4] = h;
            *(uint4*)&sAl[ar][ac + 4] = lo;
        }
        // convert + store B
        {
            uint4 h, lo;
            h.x = f2tf32(fb0.x); h.y = f2tf32(fb0.y); h.z = f2tf32(fb0.z); h.w = f2tf32(fb0.w);
            lo.x = f2tf32(fb0.x - __uint_as_float(h.x));
            lo.y = f2tf32(fb0.y - __uint_as_float(h.y));
            lo.z = f2tf32(fb0.z - __uint_as_float(h.z));
            lo.w = f2tf32(fb0.w - __uint_as_float(h.w));
            *(uint4*)&sBh[bkr][bnc] = h;
            *(uint4*)&sBl[bkr][bnc] = lo;
            h.x = f2tf32(fb1.x); h.y = f2tf32(fb1.y); h.z = f2tf32(fb1.z); h.w = f2tf32(fb1.w);
            lo.x = f2tf32(fb1.x - __uint_as_float(h.x));
            lo.y = f2tf32(fb1.y - __uint_as_float(h.y));
            lo.z = f2tf32(fb1.z - __uint_as_float(h.z));
            lo.w = f2tf32(fb1.w - __uint_as_float(h.w));
            *(uint4*)&sBh[bkr][bnc + 4] = h;
            *(uint4*)&sBl[bkr][bnc + 4] = lo;
        }
        __syncthreads();
        // prefetch next k-step
        if (kt < 15) {
            int k = (kt + 1) * 16;
            fa0 = fa1 = make_float4(0.f, 0.f, 0.f, 0.f);
            if (aval) {
                fa0 = *(const float4*)&Arow[k + ac];
                fa1 = *(const float4*)&Arow[k + ac + 4];
            }
            fb0 = *(const float4*)&W[(size_t)(k + bkr) * 256 + n0 + bnc];
            fb1 = *(const float4*)&W[(size_t)(k + bkr) * 256 + n0 + bnc + 4];
        }
        // MMA over this k16 (two k8 sub-steps)
#pragma unroll
        for (int s = 0; s < 2; s++) {
            int kb = s * 8;
            unsigned ah[4][4], al_[4][4];
#pragma unroll
            for (int i = 0; i < 4; i++) {
                int r0 = wm * 64 + i * 16 + g;
                int r1 = r0 + 8;
                ah[i][0] = sAh[r0][kb + l];
                ah[i][1] = sAh[r1][kb + l];
                ah[i][2] = sAh[r0][kb + l + 4];
                ah[i][3] = sAh[r1][kb + l + 4];
                al_[i][0] = sAl[r0][kb + l];
                al_[i][1] = sAl[r1][kb + l];
                al_[i][2] = sAl[r0][kb + l + 4];
                al_[i][3] = sAl[r1][kb + l + 4];
            }
            unsigned bh[4][2], bl_[4][2];
#pragma unroll
            for (int j = 0; j < 4; j++) {
                int nn = wn * 32 + j * 8 + g;
                bh[j][0] = sBh[kb + l][nn];
                bh[j][1] = sBh[kb + l + 4][nn];
                bl_[j][0] = sBl[kb + l][nn];
                bl_[j][1] = sBl[kb + l + 4][nn];
            }
#pragma unroll
            for (int i = 0; i < 4; i++)
#pragma unroll
                for (int j = 0; j < 4; j++) {
                    MMA_TF32(acc[i][j], ah[i], bh[j]);
                    MMA_TF32(acc[i][j], ah[i], bl_[j]);
                    MMA_TF32(acc[i][j], al_[i], bh[j]);
                }
        }
    }

    // epilogue: bias + relu
#pragma unroll
    for (int i = 0; i < 4; i++) {
        int row0 = m0 + wm * 64 + i * 16 + g;
        int row1 = row0 + 8;
#pragma unroll
        for (int j = 0; j < 4; j++) {
            int col = n0 + wn * 32 + j * 8 + 2 * l;
            float bc0 = __ldg(&bias[col]);
            float bc1 = __ldg(&bias[col + 1]);
            if (row0 < M) {
                float2 v;
                v.x = fmaxf(acc[i][j][0] + bc0, 0.f);
                v.y = fmaxf(acc[i][j][1] + bc1, 0.f);
                *(float2*)&g_bufB[(size_t)row0 * 256 + col] = v;
            }
            if (row1 < M) {
                float2 v;
                v.x = fmaxf(acc[i][j][2] + bc0, 0.f);
                v.y = fmaxf(acc[i][j][3] + bc1, 0.f);
                *(float2*)&g_bufB[(size_t)row1 * 256 + col] = v;
            }
        }
    }
}

// -------- layer-3 projection (NO bias): g_P = g_bufB @ W3 --------
__global__ void __launch_bounds__(256, 2)
gemm3_kernel(const float* __restrict__ W3, int M) {
    __shared__ float sW[256][40];
    __shared__ __align__(16) float sA[64][128];
    const int m0 = blockIdx.x * 128;
    const int tid = threadIdx.x;
    const int rt = tid >> 3;
    const int ct = tid & 7;

    for (int i = tid; i < 256 * 40; i += 256) sW[i / 40][i % 40] = __ldg(&W3[i]);

    float acc[4][5];
#pragma unroll
    for (int i = 0; i < 4; i++)
#pragma unroll
        for (int j = 0; j < 5; j++) acc[i][j] = 0.f;

    const int ar = tid >> 1;
    const int akb = (tid & 1) * 4;

    for (int k0 = 0; k0 < 256; k0 += 64) {
        __syncthreads();
#pragma unroll
        for (int pass = 0; pass < 8; pass++) {
            int ak = akb + pass * 8;
            float4 av = make_float4(0.f, 0.f, 0.f, 0.f);
            if (m0 + ar < M) av = *(const float4*)&g_bufB[(size_t)(m0 + ar) * 256 + k0 + ak];
            sA[ak + 0][ar] = av.x;
            sA[ak + 1][ar] = av.y;
            sA[ak + 2][ar] = av.z;
            sA[ak + 3][ar] = av.w;
        }
        __syncthreads();
        for (int kk = 0; kk < 64; kk++) {
            float4 a4 = *(const float4*)&sA[kk][rt * 4];
            float a[4] = {a4.x, a4.y, a4.z, a4.w};
            const float* wrow = &sW[k0 + kk][ct * 5];
            float w0 = wrow[0], w1 = wrow[1], w2 = wrow[2], w3 = wrow[3], w4 = wrow[4];
#pragma unroll
            for (int i = 0; i < 4; i++) {
                acc[i][0] += a[i] * w0;
                acc[i][1] += a[i] * w1;
                acc[i][2] += a[i] * w2;
                acc[i][3] += a[i] * w3;
                acc[i][4] += a[i] * w4;
            }
        }
    }

#pragma unroll
    for (int i = 0; i < 4; i++) {
        int row = m0 + rt * 4 + i;
        if (row < M) {
#pragma unroll
            for (int j = 0; j < 5; j++)
                g_P[(size_t)row * NCLS + ct * 5 + j] = acc[i][j];
        }
    }
}

// -------- final: out[v] = log_softmax( sum_{nbr} P[nbr] + b3 ); warp per node --------
__global__ void aggout_kernel(const float* __restrict__ b3, float* __restrict__ out, int M) {
    int warp = (blockIdx.x * blockDim.x + threadIdx.x) >> 5;
    int lane = threadIdx.x & 31;
    if (warp >= M) return;
    int s = __ldg(&g_rowptr[warp]);
    int e = __ldg(&g_rowptr[warp + 1]);
    bool act = lane < 20;
    int c0 = lane, c1 = lane + 20;
    float acc0 = 0.f, acc1 = 0.f;
    for (int j = s; j < e; j++) {
        int c = __ldg(&g_col[j]);
        const float* pr = &g_P[(size_t)c * NCLS];
        if (act) {
            acc0 += pr[c0];
            acc1 += pr[c1];
        }
    }
    float v0 = act ? acc0 + __ldg(&b3[c0]) : -INFINITY;
    float v1 = act ? acc1 + __ldg(&b3[c1]) : -INFINITY;
    float m = fmaxf(v0, v1);
#pragma unroll
    for (int o = 16; o > 0; o >>= 1) m = fmaxf(m, __shfl_xor_sync(0xFFFFFFFFu, m, o));
    float ssum = act ? (expf(v0 - m) + expf(v1 - m)) : 0.f;
#pragma unroll
    for (int o = 16; o > 0; o >>= 1) ssum += __shfl_xor_sync(0xFFFFFFFFu, ssum, o);
    float ls = logf(ssum);
    if (act) {
        out[(size_t)warp * NCLS + c0] = v0 - m - ls;
        out[(size_t)warp * NCLS + c1] = v1 - m - ls;
    }
}

__global__ void tail_kernel(float* out, int start, int total, float val) {
    int i = start + blockIdx.x * blockDim.x + threadIdx.x;
    if (i < total) out[i] = val;
}

extern "C" void kernel_launch(void* const* d_in, const int* in_sizes, int n_in,
                              void* d_out, int out_size) {
    const float* features = (const float*)d_in[0];
    const void*  ei       = d_in[1];
    const float* W1 = (const float*)d_in[4];
    const float* b1 = (const float*)d_in[5];
    const float* W2 = (const float*)d_in[6];
    const float* b2 = (const float*)d_in[7];
    const float* W3 = (const float*)d_in[8];
    const float* b3 = (const float*)d_in[9];
    float* out = (float*)d_out;

    const int N = NNODES, E = NEDGES;

    setup_kernel<<<(N + 255) / 256, 256>>>(ei);              // 1
    count_deg_kernel<<<(E + 255) / 256, 256>>>(ei);          // 2
    scan_phaseA<<<SCAN_BLOCKS, 1024>>>();                    // 3
    scan_phaseC<<<SCAN_BLOCKS, 1024>>>();                    // 4
    fill_kernel<<<(E + 255) / 256, 256>>>(ei);               // 5

    dim3 ggrid((N + 127) / 128, 2);

    agg1_kernel<<<(N * 64 + 255) / 256, 256>>>(features);    // 6 (ncu target)
    gemm_tf32_kernel<<<ggrid, 256>>>(W1, b1, N);             // 7
    aggBA_kernel<<<(N * 64 + 255) / 256, 256>>>();           // 8
    gemm_tf32_kernel<<<ggrid, 256>>>(W2, b2, N);             // 9
    gemm3_kernel<<<(N + 127) / 128, 256>>>(W3, N);           // 10
    aggout_kernel<<<(N * 32 + 255) / 256, 256>>>(b3, out, N);// 11

    int NC = N * NCLS;
    if (out_size > NC) {
        int extra = out_size - NC;
        tail_kernel<<<(extra + 255) / 256, 256>>>(out, NC, out_size, (float)(3 * N));
    }
}

// round 6
// speedup vs baseline: 2.0825x; 1.0929x over previous
#include <cuda_runtime.h>
#include <cuda_bf16.h>
#include <cstdint>
#include <math.h>

#define NNODES 50000
#define NEDGES 800000
#define FDIM   256
#define NCLS   40
#define SCAN_BLOCKS ((NNODES + 1023) / 1024)

// -------- scratch --------
__device__ float g_bufA[(size_t)NNODES * FDIM];
__device__ float g_bufB[(size_t)NNODES * FDIM];
__device__ float g_P[(size_t)NNODES * NCLS];
__device__ unsigned g_W1h[256 * 128], g_W1l[256 * 128];   // [n][kpair] packed bf16x2
__device__ unsigned g_W2h[256 * 128], g_W2l[256 * 128];
__device__ int   g_deg[NNODES];
__device__ int   g_off[NNODES];
__device__ int   g_rowptr[NNODES + 1];
__device__ int   g_col[NEDGES];
__device__ int   g_bsum[SCAN_BLOCKS];
__device__ int   g_not64 = 0;

// -------- bf16 split helpers --------
__device__ __forceinline__ void split2(float x0, float x1, unsigned& hi, unsigned& lo) {
    __nv_bfloat16 h0 = __float2bfloat16_rn(x0);
    __nv_bfloat16 h1 = __float2bfloat16_rn(x1);
    float r0 = x0 - __bfloat162float(h0);
    float r1 = x1 - __bfloat162float(h1);
    __nv_bfloat162 hp(h0, h1);
    __nv_bfloat162 lp(__float2bfloat16_rn(r0), __float2bfloat16_rn(r1));
    hi = *reinterpret_cast<unsigned*>(&hp);
    lo = *reinterpret_cast<unsigned*>(&lp);
}

// -------- W prep: split W[k][n] -> Wh/Wl [n][kp] (kp = k/2 pairs) --------
__global__ void prepW_kernel(const float* __restrict__ W1, const float* __restrict__ W2) {
    int t = blockIdx.x * blockDim.x + threadIdx.x;
    if (t >= 2 * 256 * 128) return;
    int which = t >> 15;
    int i = t & 32767;
    int n = i >> 7, kp = i & 127;
    const float* W = which ? W2 : W1;
    float x0 = __ldg(&W[(2 * kp) * 256 + n]);
    float x1 = __ldg(&W[(2 * kp + 1) * 256 + n]);
    unsigned hi, lo;
    split2(x0, x1, hi, lo);
    if (which) { g_W2h[n * 128 + kp] = hi; g_W2l[n * 128 + kp] = lo; }
    else       { g_W1h[n * 128 + kp] = hi; g_W1l[n * 128 + kp] = lo; }
}

// -------- setup + dtype detect --------
__global__ void setup_kernel(const void* __restrict__ ei) {
    int i = blockIdx.x * blockDim.x + threadIdx.x;
    if (i < NNODES) { g_deg[i] = 0; g_off[i] = 0; }
    if (blockIdx.x == 0 && threadIdx.x < 256) {
        const int* w = (const int*)ei;
        if (w[2 * threadIdx.x + 1] != 0) atomicOr(&g_not64, 1);
    }
}

__device__ __forceinline__ int edge_at(const void* ei, int idx) {
    if (g_not64 == 0) return (int)((const long long*)ei)[idx];
    return ((const int*)ei)[idx];
}

__global__ void count_deg_kernel(const void* __restrict__ ei) {
    int e = blockIdx.x * blockDim.x + threadIdx.x;
    if (e < NEDGES) {
        int d = edge_at(ei, NEDGES + e);
        if ((unsigned)d < NNODES) atomicAdd(&g_deg[d], 1);
    }
}

// -------- multiblock scan --------
__global__ void scan_phaseA() {
    int i = blockIdx.x * 1024 + threadIdx.x;
    int v = (i < NNODES) ? g_deg[i] : 0;
    int s = v;
#pragma unroll
    for (int o = 16; o > 0; o >>= 1) s += __shfl_xor_sync(0xFFFFFFFFu, s, o);
    __shared__ int ws[32];
    int w = threadIdx.x >> 5, l = threadIdx.x & 31;
    if (l == 0) ws[w] = s;
    __syncthreads();
    if (w == 0) {
        int t = ws[l];
#pragma unroll
        for (int o = 16; o > 0; o >>= 1) t += __shfl_xor_sync(0xFFFFFFFFu, t, o);
        if (l == 0) g_bsum[blockIdx.x] = t;
    }
}

__global__ void scan_phaseC() {
    int i = blockIdx.x * 1024 + threadIdx.x;
    int v = (i < NNODES) ? g_deg[i] : 0;
    int w = threadIdx.x >> 5, l = threadIdx.x & 31;
    int x = v;
#pragma unroll
    for (int o = 1; o < 32; o <<= 1) {
        int y = __shfl_up_sync(0xFFFFFFFFu, x, o);
        if (l >= o) x += y;
    }
    __shared__ int wtot[32];
    __shared__ int sboff;
    if (l == 31) wtot[w] = x;
    __syncthreads();
    if (w == 0) {
        int s = 0;
        for (int b = l; b < blockIdx.x; b += 32) s += g_bsum[b];
#pragma unroll
        for (int o = 16; o > 0; o >>= 1) s += __shfl_xor_sync(0xFFFFFFFFu, s, o);
        if (l == 0) sboff = s;
        int t = wtot[l];
#pragma unroll
        for (int o = 1; o < 32; o <<= 1) {
            int y = __shfl_up_sync(0xFFFFFFFFu, t, o);
            if (l >= o) t += y;
        }
        wtot[l] = t;
    }
    __syncthreads();
    int woff = (w > 0) ? wtot[w - 1] : 0;
    int excl = sboff + woff + x - v;
    if (i < NNODES) g_rowptr[i] = excl;
    if (i == NNODES - 1) g_rowptr[NNODES] = excl + v;
}

__global__ void fill_kernel(const void* __restrict__ ei) {
    int e = blockIdx.x * blockDim.x + threadIdx.x;
    if (e < NEDGES) {
        int s = edge_at(ei, e);
        int d = edge_at(ei, NEDGES + e);
        if ((unsigned)s < NNODES && (unsigned)d < NNODES) {
            int pos = g_rowptr[d] + atomicAdd(&g_off[d], 1);
            if ((unsigned)pos < NEDGES) g_col[pos] = s;
        }
    }
}

// -------- agg (bufB -> bufA) with fused bias + relu --------
__global__ void aggBR_kernel(const float* __restrict__ bias) {
    int t = blockIdx.x * blockDim.x + threadIdx.x;
    int v = t >> 6;
    int f = t & 63;
    if (v >= NNODES) return;
    const float4* in = (const float4*)g_bufB;
    int s = __ldg(&g_rowptr[v]);
    int e = __ldg(&g_rowptr[v + 1]);
    float4 a0 = make_float4(0.f, 0.f, 0.f, 0.f);
    float4 a1 = a0, a2 = a0, a3 = a0;
    int j = s;
    for (; j + 4 <= e; j += 4) {
        int c0 = __ldg(&g_col[j]);
        int c1 = __ldg(&g_col[j + 1]);
        int c2 = __ldg(&g_col[j + 2]);
        int c3 = __ldg(&g_col[j + 3]);
        float4 x0 = __ldg(&in[(size_t)c0 * 64 + f]);
        float4 x1 = __ldg(&in[(size_t)c1 * 64 + f]);
        float4 x2 = __ldg(&in[(size_t)c2 * 64 + f]);
        float4 x3 = __ldg(&in[(size_t)c3 * 64 + f]);
        a0.x += x0.x; a0.y += x0.y; a0.z += x0.z; a0.w += x0.w;
        a1.x += x1.x; a1.y += x1.y; a1.z += x1.z; a1.w += x1.w;
        a2.x += x2.x; a2.y += x2.y; a2.z += x2.z; a2.w += x2.w;
        a3.x += x3.x; a3.y += x3.y; a3.z += x3.z; a3.w += x3.w;
    }
    for (; j < e; j++) {
        int c = __ldg(&g_col[j]);
        float4 x = __ldg(&in[(size_t)c * 64 + f]);
        a0.x += x.x; a0.y += x.y; a0.z += x.z; a0.w += x.w;
    }
    float4 b = __ldg(&((const float4*)bias)[f]);
    float4 r;
    r.x = fmaxf((a0.x + a1.x) + (a2.x + a3.x) + b.x, 0.f);
    r.y = fmaxf((a0.y + a1.y) + (a2.y + a3.y) + b.y, 0.f);
    r.z = fmaxf((a0.z + a1.z) + (a2.z + a3.z) + b.z, 0.f);
    r.w = fmaxf((a0.w + a1.w) + (a2.w + a3.w) + b.w, 0.f);
    ((float4*)g_bufA)[(size_t)v * 64 + f] = r;
}

// -------- bf16x3 GEMM (pure): g_bufB = A @ W  --------
// Block 128x128, 8 warps (2m x 4n), warp tile 64x32, k-step 16, m16n8k16 bf16 MMA.
#define MMA_BF16(d, a, b) \
    asm volatile("mma.sync.aligned.m16n8k16.row.col.f32.bf16.bf16.f32 " \
        "{%0,%1,%2,%3}, {%4,%5,%6,%7}, {%8,%9}, {%0,%1,%2,%3};" \
        : "+f"(d[0]), "+f"(d[1]), "+f"(d[2]), "+f"(d[3]) \
        : "r"(a[0]), "r"(a[1]), "r"(a[2]), "r"(a[3]), "r"(b[0]), "r"(b[1]))

template<int LAYER>
__global__ void __launch_bounds__(256)
gemm_bf16_kernel(const float* __restrict__ Aext, int M) {
    __shared__ unsigned sAh[128][12], sAl[128][12];   // [m][kpair], cols 0..7 used
    __shared__ unsigned sBh[128][12], sBl[128][12];   // [n][kpair]
    const float* A = (LAYER == 1) ? Aext : g_bufA;
    const unsigned* Wh = (LAYER == 1) ? g_W1h : g_W2h;
    const unsigned* Wl = (LAYER == 1) ? g_W1l : g_W2l;

    const int m0 = blockIdx.x * 128;
    const int n0 = blockIdx.y * 128;
    const int tid = threadIdx.x;
    const int warp = tid >> 5, lane = tid & 31;
    const int wm = warp >> 2, wn = warp & 3;
    const int g = lane >> 2, l = lane & 3;

    const int ar = tid >> 1;            // A row 0..127
    const int ac = (tid & 1) * 8;       // A k offset (elements)
    const int kp0 = ac >> 1;            // pair offset 0/4
    const int bn = tid >> 1;            // B n row 0..127
    const int bq = (tid & 1) * 4;       // B kpair offset 0/4

    float acc[4][4][4];
#pragma unroll
    for (int i = 0; i < 4; i++)
#pragma unroll
        for (int j = 0; j < 4; j++)
#pragma unroll
            for (int q = 0; q < 4; q++) acc[i][j][q] = 0.f;

    const bool aval = (m0 + ar) < M;
    const float* Arow = A + (size_t)(m0 + ar) * 256;
    const unsigned* WhRow = Wh + (size_t)(n0 + bn) * 128;
    const unsigned* WlRow = Wl + (size_t)(n0 + bn) * 128;

    float4 fa0, fa1;
    uint4 wh, wl;
    fa0 = fa1 = make_float4(0.f, 0.f, 0.f, 0.f);
    if (aval) {
        fa0 = *(const float4*)&Arow[ac];
        fa1 = *(const float4*)&Arow[ac + 4];
    }
    wh = *(const uint4*)&WhRow[bq];
    wl = *(const uint4*)&WlRow[bq];

#pragma unroll 1
    for (int kt = 0; kt < 16; kt++) {
        if (kt > 0) __syncthreads();
        {
            uint4 h, lo;
            split2(fa0.x, fa0.y, h.x, lo.x);
            split2(fa0.z, fa0.w, h.y, lo.y);
            split2(fa1.x, fa1.y, h.z, lo.z);
            split2(fa1.z, fa1.w, h.w, lo.w);
            *(uint4*)&sAh[ar][kp0] = h;
            *(uint4*)&sAl[ar][kp0] = lo;
        }
        *(uint4*)&sBh[bn][bq] = wh;
        *(uint4*)&sBl[bn][bq] = wl;
        __syncthreads();
        if (kt < 15) {
            int k = (kt + 1) * 16;
            fa0 = fa1 = make_float4(0.f, 0.f, 0.f, 0.f);
            if (aval) {
                fa0 = *(const float4*)&Arow[k + ac];
                fa1 = *(const float4*)&Arow[k + ac + 4];
            }
            wh = *(const uint4*)&WhRow[(kt + 1) * 8 + bq];
            wl = *(const uint4*)&WlRow[(kt + 1) * 8 + bq];
        }
        unsigned ah[4][4], al_[4][4];
#pragma unroll
        for (int i = 0; i < 4; i++) {
            int r0 = wm * 64 + i * 16 + g;
            int r1 = r0 + 8;
            ah[i][0] = sAh[r0][l];
            ah[i][1] = sAh[r1][l];
            ah[i][2] = sAh[r0][l + 4];
            ah[i][3] = sAh[r1][l + 4];
            al_[i][0] = sAl[r0][l];
            al_[i][1] = sAl[r1][l];
            al_[i][2] = sAl[r0][l + 4];
            al_[i][3] = sAl[r1][l + 4];
        }
        unsigned bh[4][2], bl_[4][2];
#pragma unroll
        for (int j = 0; j < 4; j++) {
            int nn = wn * 32 + j * 8 + g;
            bh[j][0] = sBh[nn][l];
            bh[j][1] = sBh[nn][l + 4];
            bl_[j][0] = sBl[nn][l];
            bl_[j][1] = sBl[nn][l + 4];
        }
#pragma unroll
        for (int i = 0; i < 4; i++)
#pragma unroll
            for (int j = 0; j < 4; j++) {
                MMA_BF16(acc[i][j], ah[i], bh[j]);
                MMA_BF16(acc[i][j], ah[i], bl_[j]);
                MMA_BF16(acc[i][j], al_[i], bh[j]);
            }
    }

#pragma unroll
    for (int i = 0; i < 4; i++) {
        int row0 = m0 + wm * 64 + i * 16 + g;
        int row1 = row0 + 8;
#pragma unroll
        for (int j = 0; j < 4; j++) {
            int col = n0 + wn * 32 + j * 8 + 2 * l;
            if (row0 < M) {
                float2 v = {acc[i][j][0], acc[i][j][1]};
                *(float2*)&g_bufB[(size_t)row0 * 256 + col] = v;
            }
            if (row1 < M) {
                float2 v = {acc[i][j][2], acc[i][j][3]};
                *(float2*)&g_bufB[(size_t)row1 * 256 + col] = v;
            }
        }
    }
}

// -------- layer-3 projection: g_P = g_bufA @ W3 (no bias) --------
__global__ void __launch_bounds__(256, 2)
gemm3_kernel(const float* __restrict__ W3, int M) {
    __shared__ float sW[256][40];
    __shared__ __align__(16) float sA[64][128];
    const int m0 = blockIdx.x * 128;
    const int tid = threadIdx.x;
    const int rt = tid >> 3;
    const int ct = tid & 7;

    for (int i = tid; i < 256 * 40; i += 256) sW[i / 40][i % 40] = __ldg(&W3[i]);

    float acc[4][5];
#pragma unroll
    for (int i = 0; i < 4; i++)
#pragma unroll
        for (int j = 0; j < 5; j++) acc[i][j] = 0.f;

    const int ar = tid >> 1;
    const int akb = (tid & 1) * 4;

    for (int k0 = 0; k0 < 256; k0 += 64) {
        __syncthreads();
#pragma unroll
        for (int pass = 0; pass < 8; pass++) {
            int ak = akb + pass * 8;
            float4 av = make_float4(0.f, 0.f, 0.f, 0.f);
            if (m0 + ar < M) av = *(const float4*)&g_bufA[(size_t)(m0 + ar) * 256 + k0 + ak];
            sA[ak + 0][ar] = av.x;
            sA[ak + 1][ar] = av.y;
            sA[ak + 2][ar] = av.z;
            sA[ak + 3][ar] = av.w;
        }
        __syncthreads();
        for (int kk = 0; kk < 64; kk++) {
            float4 a4 = *(const float4*)&sA[kk][rt * 4];
            float a[4] = {a4.x, a4.y, a4.z, a4.w};
            const float* wrow = &sW[k0 + kk][ct * 5];
            float w0 = wrow[0], w1 = wrow[1], w2 = wrow[2], w3 = wrow[3], w4 = wrow[4];
#pragma unroll
            for (int i = 0; i < 4; i++) {
                acc[i][0] += a[i] * w0;
                acc[i][1] += a[i] * w1;
                acc[i][2] += a[i] * w2;
                acc[i][3] += a[i] * w3;
                acc[i][4] += a[i] * w4;
            }
        }
    }

#pragma unroll
    for (int i = 0; i < 4; i++) {
        int row = m0 + rt * 4 + i;
        if (row < M) {
#pragma unroll
            for (int j = 0; j < 5; j++)
                g_P[(size_t)row * NCLS + ct * 5 + j] = acc[i][j];
        }
    }
}

// -------- final: out[v] = log_softmax( agg(P)[v] + b3 ); warp per node --------
__global__ void aggout_kernel(const float* __restrict__ b3, float* __restrict__ out, int M) {
    int warp = (blockIdx.x * blockDim.x + threadIdx.x) >> 5;
    int lane = threadIdx.x & 31;
    if (warp >= M) return;
    int s = __ldg(&g_rowptr[warp]);
    int e = __ldg(&g_rowptr[warp + 1]);
    bool act = lane < 20;
    int c0 = lane, c1 = lane + 20;
    float acc0 = 0.f, acc1 = 0.f;
    for (int j = s; j < e; j++) {
        int c = __ldg(&g_col[j]);
        const float* pr = &g_P[(size_t)c * NCLS];
        if (act) {
            acc0 += pr[c0];
            acc1 += pr[c1];
        }
    }
    float v0 = act ? acc0 + __ldg(&b3[c0]) : -INFINITY;
    float v1 = act ? acc1 + __ldg(&b3[c1]) : -INFINITY;
    float m = fmaxf(v0, v1);
#pragma unroll
    for (int o = 16; o > 0; o >>= 1) m = fmaxf(m, __shfl_xor_sync(0xFFFFFFFFu, m, o));
    float ssum = act ? (expf(v0 - m) + expf(v1 - m)) : 0.f;
#pragma unroll
    for (int o = 16; o > 0; o >>= 1) ssum += __shfl_xor_sync(0xFFFFFFFFu, ssum, o);
    float ls = logf(ssum);
    if (act) {
        out[(size_t)warp * NCLS + c0] = v0 - m - ls;
        out[(size_t)warp * NCLS + c1] = v1 - m - ls;
    }
}

__global__ void tail_kernel(float* out, int start, int total, float val) {
    int i = start + blockIdx.x * blockDim.x + threadIdx.x;
    if (i < total) out[i] = val;
}

extern "C" void kernel_launch(void* const* d_in, const int* in_sizes, int n_in,
                              void* d_out, int out_size) {
    const float* features = (const float*)d_in[0];
    const void*  ei       = d_in[1];
    const float* W1 = (const float*)d_in[4];
    const float* b1 = (const float*)d_in[5];
    const float* W2 = (const float*)d_in[6];
    const float* b2 = (const float*)d_in[7];
    const float* W3 = (const float*)d_in[8];
    const float* b3 = (const float*)d_in[9];
    float* out = (float*)d_out;

    const int N = NNODES, E = NEDGES;
    dim3 ggrid((N + 127) / 128, 2);

    prepW_kernel<<<(2 * 256 * 128 + 255) / 256, 256>>>(W1, W2);   // 0
    setup_kernel<<<(N + 255) / 256, 256>>>(ei);                   // 1
    count_deg_kernel<<<(E + 255) / 256, 256>>>(ei);               // 2
    gemm_bf16_kernel<1><<<ggrid, 256>>>(features, N);             // 3  T1 = X@W1 (ncu target)
    scan_phaseA<<<SCAN_BLOCKS, 1024>>>();                         // 4
    scan_phaseC<<<SCAN_BLOCKS, 1024>>>();                         // 5
    fill_kernel<<<(E + 255) / 256, 256>>>(ei);                    // 6
    aggBR_kernel<<<(N * 64 + 255) / 256, 256>>>(b1);              // 7  H1 = relu(agg(T1)+b1)
    gemm_bf16_kernel<2><<<ggrid, 256>>>(nullptr, N);              // 8  T2 = H1@W2
    aggBR_kernel<<<(N * 64 + 255) / 256, 256>>>(b2);              // 9  H2 = relu(agg(T2)+b2)
    gemm3_kernel<<<(N + 127) / 128, 256>>>(W3, N);                // 10 P = H2@W3
    aggout_kernel<<<(N * 32 + 255) / 256, 256>>>(b3, out, N);     // 11

    int NC = N * NCLS;
    if (out_size > NC) {
        int extra = out_size - NC;
        tail_kernel<<<(extra + 255) / 256, 256>>>(out, NC, out_size, (float)(3 * N));
    }
}

// round 7
// speedup vs baseline: 2.1620x; 1.0382x over previous
#include <cuda_runtime.h>
#include <cuda_bf16.h>
#include <cstdint>
#include <math.h>

#define NNODES 50000
#define NEDGES 800000
#define FDIM   256
#define NCLS   40
#define SCAN_BLOCKS ((NNODES + 1023) / 1024)

// -------- scratch --------
__device__ float g_bufA[(size_t)NNODES * FDIM];
__device__ float g_bufB[(size_t)NNODES * FDIM];
__device__ float g_P[(size_t)NNODES * NCLS];
__device__ unsigned g_W1h[256 * 128], g_W1l[256 * 128];   // [n][kpair] packed bf16x2
__device__ unsigned g_W2h[256 * 128], g_W2l[256 * 128];
__device__ int   g_deg[NNODES];
__device__ int   g_off[NNODES];
__device__ int   g_rowptr[NNODES + 1];
__device__ int   g_col[NEDGES];
__device__ int   g_bsum[SCAN_BLOCKS];
__device__ int   g_not64 = 0;

// -------- bf16 split helpers --------
__device__ __forceinline__ void split2(float x0, float x1, unsigned& hi, unsigned& lo) {
    __nv_bfloat16 h0 = __float2bfloat16_rn(x0);
    __nv_bfloat16 h1 = __float2bfloat16_rn(x1);
    float r0 = x0 - __bfloat162float(h0);
    float r1 = x1 - __bfloat162float(h1);
    __nv_bfloat162 hp(h0, h1);
    __nv_bfloat162 lp(__float2bfloat16_rn(r0), __float2bfloat16_rn(r1));
    hi = *reinterpret_cast<unsigned*>(&hp);
    lo = *reinterpret_cast<unsigned*>(&lp);
}

// -------- W prep: split W[k][n] -> Wh/Wl [n][kp] --------
__global__ void prepW_kernel(const float* __restrict__ W1, const float* __restrict__ W2) {
    int t = blockIdx.x * blockDim.x + threadIdx.x;
    if (t >= 2 * 256 * 128) return;
    int which = t >> 15;
    int i = t & 32767;
    int n = i >> 7, kp = i & 127;
    const float* W = which ? W2 : W1;
    float x0 = __ldg(&W[(2 * kp) * 256 + n]);
    float x1 = __ldg(&W[(2 * kp + 1) * 256 + n]);
    unsigned hi, lo;
    split2(x0, x1, hi, lo);
    if (which) { g_W2h[n * 128 + kp] = hi; g_W2l[n * 128 + kp] = lo; }
    else       { g_W1h[n * 128 + kp] = hi; g_W1l[n * 128 + kp] = lo; }
}

// -------- setup + dtype detect --------
__global__ void setup_kernel(const void* __restrict__ ei) {
    int i = blockIdx.x * blockDim.x + threadIdx.x;
    if (i < NNODES) { g_deg[i] = 0; g_off[i] = 0; }
    if (blockIdx.x == 0 && threadIdx.x < 256) {
        const int* w = (const int*)ei;
        if (w[2 * threadIdx.x + 1] != 0) atomicOr(&g_not64, 1);
    }
}

__device__ __forceinline__ int edge_at(const void* ei, int idx) {
    if (g_not64 == 0) return (int)((const long long*)ei)[idx];
    return ((const int*)ei)[idx];
}

__global__ void count_deg_kernel(const void* __restrict__ ei) {
    int e = blockIdx.x * blockDim.x + threadIdx.x;
    if (e < NEDGES) {
        int d = edge_at(ei, NEDGES + e);
        if ((unsigned)d < NNODES) atomicAdd(&g_deg[d], 1);
    }
}

// -------- multiblock scan --------
__global__ void scan_phaseA() {
    int i = blockIdx.x * 1024 + threadIdx.x;
    int v = (i < NNODES) ? g_deg[i] : 0;
    int s = v;
#pragma unroll
    for (int o = 16; o > 0; o >>= 1) s += __shfl_xor_sync(0xFFFFFFFFu, s, o);
    __shared__ int ws[32];
    int w = threadIdx.x >> 5, l = threadIdx.x & 31;
    if (l == 0) ws[w] = s;
    __syncthreads();
    if (w == 0) {
        int t = ws[l];
#pragma unroll
        for (int o = 16; o > 0; o >>= 1) t += __shfl_xor_sync(0xFFFFFFFFu, t, o);
        if (l == 0) g_bsum[blockIdx.x] = t;
    }
}

__global__ void scan_phaseC() {
    int i = blockIdx.x * 1024 + threadIdx.x;
    int v = (i < NNODES) ? g_deg[i] : 0;
    int w = threadIdx.x >> 5, l = threadIdx.x & 31;
    int x = v;
#pragma unroll
    for (int o = 1; o < 32; o <<= 1) {
        int y = __shfl_up_sync(0xFFFFFFFFu, x, o);
        if (l >= o) x += y;
    }
    __shared__ int wtot[32];
    __shared__ int sboff;
    if (l == 31) wtot[w] = x;
    __syncthreads();
    if (w == 0) {
        int s = 0;
        for (int b = l; b < blockIdx.x; b += 32) s += g_bsum[b];
#pragma unroll
        for (int o = 16; o > 0; o >>= 1) s += __shfl_xor_sync(0xFFFFFFFFu, s, o);
        if (l == 0) sboff = s;
        int t = wtot[l];
#pragma unroll
        for (int o = 1; o < 32; o <<= 1) {
            int y = __shfl_up_sync(0xFFFFFFFFu, t, o);
            if (l >= o) t += y;
        }
        wtot[l] = t;
    }
    __syncthreads();
    int woff = (w > 0) ? wtot[w - 1] : 0;
    int excl = sboff + woff + x - v;
    if (i < NNODES) g_rowptr[i] = excl;
    if (i == NNODES - 1) g_rowptr[NNODES] = excl + v;
}

__global__ void fill_kernel(const void* __restrict__ ei) {
    int e = blockIdx.x * blockDim.x + threadIdx.x;
    if (e < NEDGES) {
        int s = edge_at(ei, e);
        int d = edge_at(ei, NEDGES + e);
        if ((unsigned)s < NNODES && (unsigned)d < NNODES) {
            int pos = g_rowptr[d] + atomicAdd(&g_off[d], 1);
            if ((unsigned)pos < NEDGES) g_col[pos] = s;
        }
    }
}

// -------- agg (bufB -> bufA) with fused bias + relu --------
__global__ void aggBR_kernel(const float* __restrict__ bias) {
    int t = blockIdx.x * blockDim.x + threadIdx.x;
    int v = t >> 6;
    int f = t & 63;
    if (v >= NNODES) return;
    const float4* in = (const float4*)g_bufB;
    int s = __ldg(&g_rowptr[v]);
    int e = __ldg(&g_rowptr[v + 1]);
    float4 a0 = make_float4(0.f, 0.f, 0.f, 0.f);
    float4 a1 = a0, a2 = a0, a3 = a0;
    int j = s;
    for (; j + 4 <= e; j += 4) {
        int c0 = __ldg(&g_col[j]);
        int c1 = __ldg(&g_col[j + 1]);
        int c2 = __ldg(&g_col[j + 2]);
        int c3 = __ldg(&g_col[j + 3]);
        float4 x0 = __ldg(&in[(size_t)c0 * 64 + f]);
        float4 x1 = __ldg(&in[(size_t)c1 * 64 + f]);
        float4 x2 = __ldg(&in[(size_t)c2 * 64 + f]);
        float4 x3 = __ldg(&in[(size_t)c3 * 64 + f]);
        a0.x += x0.x; a0.y += x0.y; a0.z += x0.z; a0.w += x0.w;
        a1.x += x1.x; a1.y += x1.y; a1.z += x1.z; a1.w += x1.w;
        a2.x += x2.x; a2.y += x2.y; a2.z += x2.z; a2.w += x2.w;
        a3.x += x3.x; a3.y += x3.y; a3.z += x3.z; a3.w += x3.w;
    }
    for (; j < e; j++) {
        int c = __ldg(&g_col[j]);
        float4 x = __ldg(&in[(size_t)c * 64 + f]);
        a0.x += x.x; a0.y += x.y; a0.z += x.z; a0.w += x.w;
    }
    float4 b = __ldg(&((const float4*)bias)[f]);
    float4 r;
    r.x = fmaxf((a0.x + a1.x) + (a2.x + a3.x) + b.x, 0.f);
    r.y = fmaxf((a0.y + a1.y) + (a2.y + a3.y) + b.y, 0.f);
    r.z = fmaxf((a0.z + a1.z) + (a2.z + a3.z) + b.z, 0.f);
    r.w = fmaxf((a0.w + a1.w) + (a2.w + a3.w) + b.w, 0.f);
    ((float4*)g_bufA)[(size_t)v * 64 + f] = r;
}

// -------- bf16x3 GEMM: g_bufB = A @ W --------
// Block 64x128, 8 warps (2m x 4n), warp tile 32x32, k-step 16, m16n8k16 bf16 MMA.
#define MMA_BF16(d, a, b) \
    asm volatile("mma.sync.aligned.m16n8k16.row.col.f32.bf16.bf16.f32 " \
        "{%0,%1,%2,%3}, {%4,%5,%6,%7}, {%8,%9}, {%0,%1,%2,%3};" \
        : "+f"(d[0]), "+f"(d[1]), "+f"(d[2]), "+f"(d[3]) \
        : "r"(a[0]), "r"(a[1]), "r"(a[2]), "r"(a[3]), "r"(b[0]), "r"(b[1]))

template<int LAYER>
__global__ void __launch_bounds__(256, 2)
gemm_bf16_kernel(const float* __restrict__ Aext, int M) {
    __shared__ unsigned sAh[64][12], sAl[64][12];     // [m][kpair], cols 0..7 used
    __shared__ unsigned sBh[128][12], sBl[128][12];   // [n][kpair]
    const float* A = (LAYER == 1) ? Aext : g_bufA;
    const unsigned* Wh = (LAYER == 1) ? g_W1h : g_W2h;
    const unsigned* Wl = (LAYER == 1) ? g_W1l : g_W2l;

    const int m0 = blockIdx.x * 64;
    const int n0 = blockIdx.y * 128;
    const int tid = threadIdx.x;
    const int warp = tid >> 5, lane = tid & 31;
    const int wm = warp >> 2, wn = warp & 3;     // 2 x 4 warps
    const int g = lane >> 2, l = lane & 3;

    const int ar = tid >> 2;            // A row 0..63
    const int ac = (tid & 3) * 4;       // A k offset (elements, 0/4/8/12)
    const int akp = ac >> 1;            // pair offset 0/2/4/6
    const int bn = tid >> 1;            // B n row 0..127
    const int bq = (tid & 1) * 4;       // B kpair offset 0/4

    float acc[2][4][4];
#pragma unroll
    for (int i = 0; i < 2; i++)
#pragma unroll
        for (int j = 0; j < 4; j++)
#pragma unroll
            for (int q = 0; q < 4; q++) acc[i][j][q] = 0.f;

    const bool aval = (m0 + ar) < M;
    const float* Arow = A + (size_t)(m0 + ar) * 256;
    const unsigned* WhRow = Wh + (size_t)(n0 + bn) * 128;
    const unsigned* WlRow = Wl + (size_t)(n0 + bn) * 128;

    float4 fa;
    uint4 wh, wl;
    fa = make_float4(0.f, 0.f, 0.f, 0.f);
    if (aval) fa = *(const float4*)&Arow[ac];
    wh = *(const uint4*)&WhRow[bq];
    wl = *(const uint4*)&WlRow[bq];

#pragma unroll 1
    for (int kt = 0; kt < 16; kt++) {
        if (kt > 0) __syncthreads();
        {
            uint2 h, lo;
            split2(fa.x, fa.y, h.x, lo.x);
            split2(fa.z, fa.w, h.y, lo.y);
            *(uint2*)&sAh[ar][akp] = h;
            *(uint2*)&sAl[ar][akp] = lo;
        }
        *(uint4*)&sBh[bn][bq] = wh;
        *(uint4*)&sBl[bn][bq] = wl;
        __syncthreads();
        if (kt < 15) {
            int k = (kt + 1) * 16;
            fa = make_float4(0.f, 0.f, 0.f, 0.f);
            if (aval) fa = *(const float4*)&Arow[k + ac];
            wh = *(const uint4*)&WhRow[(kt + 1) * 8 + bq];
            wl = *(const uint4*)&WlRow[(kt + 1) * 8 + bq];
        }
        unsigned ah[2][4], al_[2][4];
#pragma unroll
        for (int i = 0; i < 2; i++) {
            int r0 = wm * 32 + i * 16 + g;
            int r1 = r0 + 8;
            ah[i][0] = sAh[r0][l];
            ah[i][1] = sAh[r1][l];
            ah[i][2] = sAh[r0][l + 4];
            ah[i][3] = sAh[r1][l + 4];
            al_[i][0] = sAl[r0][l];
            al_[i][1] = sAl[r1][l];
            al_[i][2] = sAl[r0][l + 4];
            al_[i][3] = sAl[r1][l + 4];
        }
        unsigned bh[4][2], bl_[4][2];
#pragma unroll
        for (int j = 0; j < 4; j++) {
            int nn = wn * 32 + j * 8 + g;
            bh[j][0] = sBh[nn][l];
            bh[j][1] = sBh[nn][l + 4];
            bl_[j][0] = sBl[nn][l];
            bl_[j][1] = sBl[nn][l + 4];
        }
#pragma unroll
        for (int i = 0; i < 2; i++)
#pragma unroll
            for (int j = 0; j < 4; j++) {
                MMA_BF16(acc[i][j], ah[i], bh[j]);
                MMA_BF16(acc[i][j], ah[i], bl_[j]);
                MMA_BF16(acc[i][j], al_[i], bh[j]);
            }
    }

#pragma unroll
    for (int i = 0; i < 2; i++) {
        int row0 = m0 + wm * 32 + i * 16 + g;
        int row1 = row0 + 8;
#pragma unroll
        for (int j = 0; j < 4; j++) {
            int col = n0 + wn * 32 + j * 8 + 2 * l;
            if (row0 < M) {
                float2 v = {acc[i][j][0], acc[i][j][1]};
                *(float2*)&g_bufB[(size_t)row0 * 256 + col] = v;
            }
            if (row1 < M) {
                float2 v = {acc[i][j][2], acc[i][j][3]};
                *(float2*)&g_bufB[(size_t)row1 * 256 + col] = v;
            }
        }
    }
}

// -------- layer-3 projection: g_P = g_bufA @ W3 (no bias) --------
__global__ void __launch_bounds__(256, 2)
gemm3_kernel(const float* __restrict__ W3, int M) {
    __shared__ float sW[256][40];
    __shared__ __align__(16) float sA[64][128];
    const int m0 = blockIdx.x * 128;
    const int tid = threadIdx.x;
    const int rt = tid >> 3;
    const int ct = tid & 7;

    for (int i = tid; i < 256 * 40; i += 256) sW[i / 40][i % 40] = __ldg(&W3[i]);

    float acc[4][5];
#pragma unroll
    for (int i = 0; i < 4; i++)
#pragma unroll
        for (int j = 0; j < 5; j++) acc[i][j] = 0.f;

    const int ar = tid >> 1;
    const int akb = (tid & 1) * 4;

    for (int k0 = 0; k0 < 256; k0 += 64) {
        __syncthreads();
#pragma unroll
        for (int pass = 0; pass < 8; pass++) {
            int ak = akb + pass * 8;
            float4 av = make_float4(0.f, 0.f, 0.f, 0.f);
            if (m0 + ar < M) av = *(const float4*)&g_bufA[(size_t)(m0 + ar) * 256 + k0 + ak];
            sA[ak + 0][ar] = av.x;
            sA[ak + 1][ar] = av.y;
            sA[ak + 2][ar] = av.z;
            sA[ak + 3][ar] = av.w;
        }
        __syncthreads();
        for (int kk = 0; kk < 64; kk++) {
            float4 a4 = *(const float4*)&sA[kk][rt * 4];
            float a[4] = {a4.x, a4.y, a4.z, a4.w};
            const float* wrow = &sW[k0 + kk][ct * 5];
            float w0 = wrow[0], w1 = wrow[1], w2 = wrow[2], w3 = wrow[3], w4 = wrow[4];
#pragma unroll
            for (int i = 0; i < 4; i++) {
                acc[i][0] += a[i] * w0;
                acc[i][1] += a[i] * w1;
                acc[i][2] += a[i] * w2;
                acc[i][3] += a[i] * w3;
                acc[i][4] += a[i] * w4;
            }
        }
    }

#pragma unroll
    for (int i = 0; i < 4; i++) {
        int row = m0 + rt * 4 + i;
        if (row < M) {
#pragma unroll
            for (int j = 0; j < 5; j++)
                g_P[(size_t)row * NCLS + ct * 5 + j] = acc[i][j];
        }
    }
}

// -------- final: out[v] = log_softmax( agg(P)[v] + b3 ); warp per node --------
__global__ void aggout_kernel(const float* __restrict__ b3, float* __restrict__ out, int M) {
    int warp = (blockIdx.x * blockDim.x + threadIdx.x) >> 5;
    int lane = threadIdx.x & 31;
    if (warp >= M) return;
    int s = __ldg(&g_rowptr[warp]);
    int e = __ldg(&g_rowptr[warp + 1]);
    bool act = lane < 20;
    int c0 = lane, c1 = lane + 20;
    float acc0 = 0.f, acc1 = 0.f;
    for (int j = s; j < e; j++) {
        int c = __ldg(&g_col[j]);
        const float* pr = &g_P[(size_t)c * NCLS];
        if (act) {
            acc0 += pr[c0];
            acc1 += pr[c1];
        }
    }
    float v0 = act ? acc0 + __ldg(&b3[c0]) : -INFINITY;
    float v1 = act ? acc1 + __ldg(&b3[c1]) : -INFINITY;
    float m = fmaxf(v0, v1);
#pragma unroll
    for (int o = 16; o > 0; o >>= 1) m = fmaxf(m, __shfl_xor_sync(0xFFFFFFFFu, m, o));
    float ssum = act ? (expf(v0 - m) + expf(v1 - m)) : 0.f;
#pragma unroll
    for (int o = 16; o > 0; o >>= 1) ssum += __shfl_xor_sync(0xFFFFFFFFu, ssum, o);
    float ls = logf(ssum);
    if (act) {
        out[(size_t)warp * NCLS + c0] = v0 - m - ls;
        out[(size_t)warp * NCLS + c1] = v1 - m - ls;
    }
}

__global__ void tail_kernel(float* out, int start, int total, float val) {
    int i = start + blockIdx.x * blockDim.x + threadIdx.x;
    if (i < total) out[i] = val;
}

extern "C" void kernel_launch(void* const* d_in, const int* in_sizes, int n_in,
                              void* d_out, int out_size) {
    const float* features = (const float*)d_in[0];
    const void*  ei       = d_in[1];
    const float* W1 = (const float*)d_in[4];
    const float* b1 = (const float*)d_in[5];
    const float* W2 = (const float*)d_in[6];
    const float* b2 = (const float*)d_in[7];
    const float* W3 = (const float*)d_in[8];
    const float* b3 = (const float*)d_in[9];
    float* out = (float*)d_out;

    const int N = NNODES, E = NEDGES;
    dim3 ggrid((N + 63) / 64, 2);

    prepW_kernel<<<(2 * 256 * 128 + 255) / 256, 256>>>(W1, W2);   // 0
    setup_kernel<<<(N + 255) / 256, 256>>>(ei);                   // 1
    count_deg_kernel<<<(E + 255) / 256, 256>>>(ei);               // 2
    gemm_bf16_kernel<1><<<ggrid, 256>>>(features, N);             // 3  T1 = X@W1 (ncu target)
    scan_phaseA<<<SCAN_BLOCKS, 1024>>>();                         // 4
    scan_phaseC<<<SCAN_BLOCKS, 1024>>>();                         // 5
    fill_kernel<<<(E + 255) / 256, 256>>>(ei);                    // 6
    aggBR_kernel<<<(N * 64 + 255) / 256, 256>>>(b1);              // 7  H1 = relu(agg(T1)+b1)
    gemm_bf16_kernel<2><<<ggrid, 256>>>(nullptr, N);              // 8  T2 = H1@W2
    aggBR_kernel<<<(N * 64 + 255) / 256, 256>>>(b2);              // 9  H2 = relu(agg(T2)+b2)
    gemm3_kernel<<<(N + 127) / 128, 256>>>(W3, N);                // 10 P = H2@W3
    aggout_kernel<<<(N * 32 + 255) / 256, 256>>>(b3, out, N);     // 11

    int NC = N * NCLS;
    if (out_size > NC) {
        int extra = out_size - NC;
        tail_kernel<<<(extra + 255) / 256, 256>>>(out, NC, out_size, (float)(3 * N));
    }
}

// round 8
// speedup vs baseline: 2.2962x; 1.0621x over previous
#include <cuda_runtime.h>
#include <cuda_bf16.h>
#include <cstdint>
#include <math.h>

#define NNODES 50000
#define NEDGES 800000
#define FDIM   256
#define NCLS   40
#define SCAN_BLOCKS ((NNODES + 1023) / 1024)

// -------- scratch --------
__device__ float g_bufA[(size_t)NNODES * FDIM];
__device__ float g_bufB[(size_t)NNODES * FDIM];
__device__ float g_P[(size_t)NNODES * NCLS];
__device__ unsigned g_W1h[256 * 128], g_W1l[256 * 128];   // [n][kpair] packed bf16x2
__device__ unsigned g_W2h[256 * 128], g_W2l[256 * 128];
__device__ int   g_deg[NNODES];
__device__ int   g_off[NNODES];
__device__ int   g_rowptr[NNODES + 1];
__device__ int   g_col[NEDGES];
__device__ int   g_bsum[SCAN_BLOCKS];
__device__ int   g_not64 = 0;

// -------- bf16 split helpers --------
__device__ __forceinline__ void split2(float x0, float x1, unsigned& hi, unsigned& lo) {
    __nv_bfloat16 h0 = __float2bfloat16_rn(x0);
    __nv_bfloat16 h1 = __float2bfloat16_rn(x1);
    float r0 = x0 - __bfloat162float(h0);
    float r1 = x1 - __bfloat162float(h1);
    __nv_bfloat162 hp(h0, h1);
    __nv_bfloat162 lp(__float2bfloat16_rn(r0), __float2bfloat16_rn(r1));
    hi = *reinterpret_cast<unsigned*>(&hp);
    lo = *reinterpret_cast<unsigned*>(&lp);
}

// -------- W prep --------
__global__ void prepW_kernel(const float* __restrict__ W1, const float* __restrict__ W2) {
    int t = blockIdx.x * blockDim.x + threadIdx.x;
    if (t >= 2 * 256 * 128) return;
    int which = t >> 15;
    int i = t & 32767;
    int n = i >> 7, kp = i & 127;
    const float* W = which ? W2 : W1;
    float x0 = __ldg(&W[(2 * kp) * 256 + n]);
    float x1 = __ldg(&W[(2 * kp + 1) * 256 + n]);
    unsigned hi, lo;
    split2(x0, x1, hi, lo);
    if (which) { g_W2h[n * 128 + kp] = hi; g_W2l[n * 128 + kp] = lo; }
    else       { g_W1h[n * 128 + kp] = hi; g_W1l[n * 128 + kp] = lo; }
}

// -------- setup + dtype detect --------
__global__ void setup_kernel(const void* __restrict__ ei) {
    int i = blockIdx.x * blockDim.x + threadIdx.x;
    if (i < NNODES) { g_deg[i] = 0; g_off[i] = 0; }
    if (blockIdx.x == 0 && threadIdx.x < 256) {
        const int* w = (const int*)ei;
        if (w[2 * threadIdx.x + 1] != 0) atomicOr(&g_not64, 1);
    }
}

__device__ __forceinline__ int edge_at(const void* ei, int idx) {
    if (g_not64 == 0) return (int)((const long long*)ei)[idx];
    return ((const int*)ei)[idx];
}

__global__ void count_deg_kernel(const void* __restrict__ ei) {
    int e = blockIdx.x * blockDim.x + threadIdx.x;
    if (e < NEDGES) {
        int d = edge_at(ei, NEDGES + e);
        if ((unsigned)d < NNODES) atomicAdd(&g_deg[d], 1);
    }
}

// -------- multiblock scan --------
__global__ void scan_phaseA() {
    int i = blockIdx.x * 1024 + threadIdx.x;
    int v = (i < NNODES) ? g_deg[i] : 0;
    int s = v;
#pragma unroll
    for (int o = 16; o > 0; o >>= 1) s += __shfl_xor_sync(0xFFFFFFFFu, s, o);
    __shared__ int ws[32];
    int w = threadIdx.x >> 5, l = threadIdx.x & 31;
    if (l == 0) ws[w] = s;
    __syncthreads();
    if (w == 0) {
        int t = ws[l];
#pragma unroll
        for (int o = 16; o > 0; o >>= 1) t += __shfl_xor_sync(0xFFFFFFFFu, t, o);
        if (l == 0) g_bsum[blockIdx.x] = t;
    }
}

__global__ void scan_phaseC() {
    int i = blockIdx.x * 1024 + threadIdx.x;
    int v = (i < NNODES) ? g_deg[i] : 0;
    int w = threadIdx.x >> 5, l = threadIdx.x & 31;
    int x = v;
#pragma unroll
    for (int o = 1; o < 32; o <<= 1) {
        int y = __shfl_up_sync(0xFFFFFFFFu, x, o);
        if (l >= o) x += y;
    }
    __shared__ int wtot[32];
    __shared__ int sboff;
    if (l == 31) wtot[w] = x;
    __syncthreads();
    if (w == 0) {
        int s = 0;
        for (int b = l; b < blockIdx.x; b += 32) s += g_bsum[b];
#pragma unroll
        for (int o = 16; o > 0; o >>= 1) s += __shfl_xor_sync(0xFFFFFFFFu, s, o);
        if (l == 0) sboff = s;
        int t = wtot[l];
#pragma unroll
        for (int o = 1; o < 32; o <<= 1) {
            int y = __shfl_up_sync(0xFFFFFFFFu, t, o);
            if (l >= o) t += y;
        }
        wtot[l] = t;
    }
    __syncthreads();
    int woff = (w > 0) ? wtot[w - 1] : 0;
    int excl = sboff + woff + x - v;
    if (i < NNODES) g_rowptr[i] = excl;
    if (i == NNODES - 1) g_rowptr[NNODES] = excl + v;
}

__global__ void fill_kernel(const void* __restrict__ ei) {
    int e = blockIdx.x * blockDim.x + threadIdx.x;
    if (e < NEDGES) {
        int s = edge_at(ei, e);
        int d = edge_at(ei, NEDGES + e);
        if ((unsigned)s < NNODES && (unsigned)d < NNODES) {
            int pos = g_rowptr[d] + atomicAdd(&g_off[d], 1);
            if ((unsigned)pos < NEDGES) g_col[pos] = s;
        }
    }
}

// -------- agg (bufB -> bufA) with fused bias + relu --------
__global__ void aggBR_kernel(const float* __restrict__ bias) {
    int t = blockIdx.x * blockDim.x + threadIdx.x;
    int v = t >> 6;
    int f = t & 63;
    if (v >= NNODES) return;
    const float4* in = (const float4*)g_bufB;
    int s = __ldg(&g_rowptr[v]);
    int e = __ldg(&g_rowptr[v + 1]);
    float4 a0 = make_float4(0.f, 0.f, 0.f, 0.f);
    float4 a1 = a0, a2 = a0, a3 = a0;
    int j = s;
    for (; j + 4 <= e; j += 4) {
        int c0 = __ldg(&g_col[j]);
        int c1 = __ldg(&g_col[j + 1]);
        int c2 = __ldg(&g_col[j + 2]);
        int c3 = __ldg(&g_col[j + 3]);
        float4 x0 = __ldg(&in[(size_t)c0 * 64 + f]);
        float4 x1 = __ldg(&in[(size_t)c1 * 64 + f]);
        float4 x2 = __ldg(&in[(size_t)c2 * 64 + f]);
        float4 x3 = __ldg(&in[(size_t)c3 * 64 + f]);
        a0.x += x0.x; a0.y += x0.y; a0.z += x0.z; a0.w += x0.w;
        a1.x += x1.x; a1.y += x1.y; a1.z += x1.z; a1.w += x1.w;
        a2.x += x2.x; a2.y += x2.y; a2.z += x2.z; a2.w += x2.w;
        a3.x += x3.x; a3.y += x3.y; a3.z += x3.z; a3.w += x3.w;
    }
    for (; j < e; j++) {
        int c = __ldg(&g_col[j]);
        float4 x = __ldg(&in[(size_t)c * 64 + f]);
        a0.x += x.x; a0.y += x.y; a0.z += x.z; a0.w += x.w;
    }
    float4 b = __ldg(&((const float4*)bias)[f]);
    float4 r;
    r.x = fmaxf((a0.x + a1.x) + (a2.x + a3.x) + b.x, 0.f);
    r.y = fmaxf((a0.y + a1.y) + (a2.y + a3.y) + b.y, 0.f);
    r.z = fmaxf((a0.z + a1.z) + (a2.z + a3.z) + b.z, 0.f);
    r.w = fmaxf((a0.w + a1.w) + (a2.w + a3.w) + b.w, 0.f);
    ((float4*)g_bufA)[(size_t)v * 64 + f] = r;
}

// -------- bf16x3 GEMM with ldmatrix + double-buffered smem --------
// Block 64x128, 8 warps (2m x 4n), warp tile 32x32, k-step 16, m16n8k16 bf16 MMA.
#define MMA_BF16(d, a, b) \
    asm volatile("mma.sync.aligned.m16n8k16.row.col.f32.bf16.bf16.f32 " \
        "{%0,%1,%2,%3}, {%4,%5,%6,%7}, {%8,%9}, {%0,%1,%2,%3};" \
        : "+f"(d[0]), "+f"(d[1]), "+f"(d[2]), "+f"(d[3]) \
        : "r"(a[0]), "r"(a[1]), "r"(a[2]), "r"(a[3]), "r"(b[0]), "r"(b[1]))

#define LDSM4(r0, r1, r2, r3, addr) \
    asm volatile("ldmatrix.sync.aligned.m8n8.x4.shared.b16 {%0,%1,%2,%3}, [%4];" \
        : "=r"(r0), "=r"(r1), "=r"(r2), "=r"(r3) : "r"(addr))

#define A_BUF_BYTES (64 * 12 * 4)
#define B_BUF_BYTES (128 * 12 * 4)

template<int LAYER>
__global__ void __launch_bounds__(256, 2)
gemm_bf16_kernel(const float* __restrict__ Aext, int M) {
    __shared__ unsigned sAh[2][64][12], sAl[2][64][12];     // [buf][m][kpair] (8 of 12 used)
    __shared__ unsigned sBh[2][128][12], sBl[2][128][12];   // [buf][n][kpair]
    const float* A = (LAYER == 1) ? Aext : g_bufA;
    const unsigned* Wh = (LAYER == 1) ? g_W1h : g_W2h;
    const unsigned* Wl = (LAYER == 1) ? g_W1l : g_W2l;

    const int m0 = blockIdx.x * 64;
    const int n0 = blockIdx.y * 128;
    const int tid = threadIdx.x;
    const int warp = tid >> 5, lane = tid & 31;
    const int wm = warp >> 2, wn = warp & 3;     // 2 x 4 warps
    const int g = lane >> 2, l = lane & 3;

    // smem writers
    const int ar = tid >> 2;            // A row 0..63
    const int ac = (tid & 3) * 4;       // A k element offset
    const int akp = ac >> 1;            // pair offset 0/2/4/6
    const int bn = tid >> 1;            // B n row 0..127
    const int bq = (tid & 1) * 4;       // B kpair offset 0/4

    // ldmatrix source addresses (buffer 0)
    const int a_row = wm * 32 + (lane & 15);
    const int a_col = (lane >> 4) * 4;
    const int b_row = wn * 32 + ((lane >> 4) << 3) + (lane & 7);
    const int b_col = ((lane >> 3) & 1) * 4;
    const unsigned aAh = (unsigned)__cvta_generic_to_shared(&sAh[0][a_row][a_col]);
    const unsigned aAl = (unsigned)__cvta_generic_to_shared(&sAl[0][a_row][a_col]);
    const unsigned aBh = (unsigned)__cvta_generic_to_shared(&sBh[0][b_row][b_col]);
    const unsigned aBl = (unsigned)__cvta_generic_to_shared(&sBl[0][b_row][b_col]);

    float acc[2][4][4];
#pragma unroll
    for (int i = 0; i < 2; i++)
#pragma unroll
        for (int j = 0; j < 4; j++)
#pragma unroll
            for (int q = 0; q < 4; q++) acc[i][j][q] = 0.f;

    const bool aval = (m0 + ar) < M;
    const float* Arow = A + (size_t)(m0 + ar) * 256;
    const unsigned* WhRow = Wh + (size_t)(n0 + bn) * 128;
    const unsigned* WlRow = Wl + (size_t)(n0 + bn) * 128;

    float4 fa = make_float4(0.f, 0.f, 0.f, 0.f);
    if (aval) fa = *(const float4*)&Arow[ac];
    uint4 wh = *(const uint4*)&WhRow[bq];
    uint4 wl = *(const uint4*)&WlRow[bq];

    int p = 0;
#pragma unroll 1
    for (int kt = 0; kt < 16; kt++) {
        // write prefetched tile into buffer p
        {
            uint2 h, lo;
            split2(fa.x, fa.y, h.x, lo.x);
            split2(fa.z, fa.w, h.y, lo.y);
            *(uint2*)&sAh[p][ar][akp] = h;
            *(uint2*)&sAl[p][ar][akp] = lo;
        }
        *(uint4*)&sBh[p][bn][bq] = wh;
        *(uint4*)&sBl[p][bn][bq] = wl;
        __syncthreads();
        // prefetch next k-step from gmem
        if (kt < 15) {
            int k = (kt + 1) * 16;
            fa = make_float4(0.f, 0.f, 0.f, 0.f);
            if (aval) fa = *(const float4*)&Arow[k + ac];
            wh = *(const uint4*)&WhRow[(kt + 1) * 8 + bq];
            wl = *(const uint4*)&WlRow[(kt + 1) * 8 + bq];
        }
        // fragment loads via ldmatrix
        const unsigned offA = (unsigned)(p * A_BUF_BYTES);
        const unsigned offB = (unsigned)(p * B_BUF_BYTES);
        unsigned ah[2][4], al_[2][4], bh[4][2], bl_[4][2];
        LDSM4(ah[0][0], ah[0][1], ah[0][2], ah[0][3], aAh + offA);
        LDSM4(ah[1][0], ah[1][1], ah[1][2], ah[1][3], aAh + offA + 16 * 48);
        LDSM4(al_[0][0], al_[0][1], al_[0][2], al_[0][3], aAl + offA);
        LDSM4(al_[1][0], al_[1][1], al_[1][2], al_[1][3], aAl + offA + 16 * 48);
        LDSM4(bh[0][0], bh[0][1], bh[1][0], bh[1][1], aBh + offB);
        LDSM4(bh[2][0], bh[2][1], bh[3][0], bh[3][1], aBh + offB + 16 * 48);
        LDSM4(bl_[0][0], bl_[0][1], bl_[1][0], bl_[1][1], aBl + offB);
        LDSM4(bl_[2][0], bl_[2][1], bl_[3][0], bl_[3][1], aBl + offB + 16 * 48);
#pragma unroll
        for (int i = 0; i < 2; i++)
#pragma unroll
            for (int j = 0; j < 4; j++) {
                MMA_BF16(acc[i][j], ah[i], bh[j]);
                MMA_BF16(acc[i][j], ah[i], bl_[j]);
                MMA_BF16(acc[i][j], al_[i], bh[j]);
            }
        p ^= 1;
    }

#pragma unroll
    for (int i = 0; i < 2; i++) {
        int row0 = m0 + wm * 32 + i * 16 + g;
        int row1 = row0 + 8;
#pragma unroll
        for (int j = 0; j < 4; j++) {
            int col = n0 + wn * 32 + j * 8 + 2 * l;
            if (row0 < M) {
                float2 v = {acc[i][j][0], acc[i][j][1]};
                *(float2*)&g_bufB[(size_t)row0 * 256 + col] = v;
            }
            if (row1 < M) {
                float2 v = {acc[i][j][2], acc[i][j][3]};
                *(float2*)&g_bufB[(size_t)row1 * 256 + col] = v;
            }
        }
    }
}

// -------- layer-3 projection: g_P = g_bufA @ W3 (no bias) --------
__global__ void __launch_bounds__(256, 2)
gemm3_kernel(const float* __restrict__ W3, int M) {
    __shared__ float sW[256][40];
    __shared__ __align__(16) float sA[64][128];
    const int m0 = blockIdx.x * 128;
    const int tid = threadIdx.x;
    const int rt = tid >> 3;
    const int ct = tid & 7;

    for (int i = tid; i < 256 * 40; i += 256) sW[i / 40][i % 40] = __ldg(&W3[i]);

    float acc[4][5];
#pragma unroll
    for (int i = 0; i < 4; i++)
#pragma unroll
        for (int j = 0; j < 5; j++) acc[i][j] = 0.f;

    const int ar = tid >> 1;
    const int akb = (tid & 1) * 4;

    for (int k0 = 0; k0 < 256; k0 += 64) {
        __syncthreads();
#pragma unroll
        for (int pass = 0; pass < 8; pass++) {
            int ak = akb + pass * 8;
            float4 av = make_float4(0.f, 0.f, 0.f, 0.f);
            if (m0 + ar < M) av = *(const float4*)&g_bufA[(size_t)(m0 + ar) * 256 + k0 + ak];
            sA[ak + 0][ar] = av.x;
            sA[ak + 1][ar] = av.y;
            sA[ak + 2][ar] = av.z;
            sA[ak + 3][ar] = av.w;
        }
        __syncthreads();
        for (int kk = 0; kk < 64; kk++) {
            float4 a4 = *(const float4*)&sA[kk][rt * 4];
            float a[4] = {a4.x, a4.y, a4.z, a4.w};
            const float* wrow = &sW[k0 + kk][ct * 5];
            float w0 = wrow[0], w1 = wrow[1], w2 = wrow[2], w3 = wrow[3], w4 = wrow[4];
#pragma unroll
            for (int i = 0; i < 4; i++) {
                acc[i][0] += a[i] * w0;
                acc[i][1] += a[i] * w1;
                acc[i][2] += a[i] * w2;
                acc[i][3] += a[i] * w3;
                acc[i][4] += a[i] * w4;
            }
        }
    }

#pragma unroll
    for (int i = 0; i < 4; i++) {
        int row = m0 + rt * 4 + i;
        if (row < M) {
#pragma unroll
            for (int j = 0; j < 5; j++)
                g_P[(size_t)row * NCLS + ct * 5 + j] = acc[i][j];
        }
    }
}

// -------- final: out[v] = log_softmax( agg(P)[v] + b3 ); warp per node --------
__global__ void aggout_kernel(const float* __restrict__ b3, float* __restrict__ out, int M) {
    int warp = (blockIdx.x * blockDim.x + threadIdx.x) >> 5;
    int lane = threadIdx.x & 31;
    if (warp >= M) return;
    int s = __ldg(&g_rowptr[warp]);
    int e = __ldg(&g_rowptr[warp + 1]);
    bool act = lane < 20;
    int c0 = lane, c1 = lane + 20;
    float acc0 = 0.f, acc1 = 0.f;
    for (int j = s; j < e; j++) {
        int c = __ldg(&g_col[j]);
        const float* pr = &g_P[(size_t)c * NCLS];
        if (act) {
            acc0 += pr[c0];
            acc1 += pr[c1];
        }
    }
    float v0 = act ? acc0 + __ldg(&b3[c0]) : -INFINITY;
    float v1 = act ? acc1 + __ldg(&b3[c1]) : -INFINITY;
    float m = fmaxf(v0, v1);
#pragma unroll
    for (int o = 16; o > 0; o >>= 1) m = fmaxf(m, __shfl_xor_sync(0xFFFFFFFFu, m, o));
    float ssum = act ? (expf(v0 - m) + expf(v1 - m)) : 0.f;
#pragma unroll
    for (int o = 16; o > 0; o >>= 1) ssum += __shfl_xor_sync(0xFFFFFFFFu, ssum, o);
    float ls = logf(ssum);
    if (act) {
        out[(size_t)warp * NCLS + c0] = v0 - m - ls;
        out[(size_t)warp * NCLS + c1] = v1 - m - ls;
    }
}

__global__ void tail_kernel(float* out, int start, int total, float val) {
    int i = start + blockIdx.x * blockDim.x + threadIdx.x;
    if (i < total) out[i] = val;
}

extern "C" void kernel_launch(void* const* d_in, const int* in_sizes, int n_in,
                              void* d_out, int out_size) {
    const float* features = (const float*)d_in[0];
    const void*  ei       = d_in[1];
    const float* W1 = (const float*)d_in[4];
    const float* b1 = (const float*)d_in[5];
    const float* W2 = (const float*)d_in[6];
    const float* b2 = (const float*)d_in[7];
    const float* W3 = (const float*)d_in[8];
    const float* b3 = (const float*)d_in[9];
    float* out = (float*)d_out;

    const int N = NNODES, E = NEDGES;
    dim3 ggrid((N + 63) / 64, 2);

    prepW_kernel<<<(2 * 256 * 128 + 255) / 256, 256>>>(W1, W2);   // 0
    setup_kernel<<<(N + 255) / 256, 256>>>(ei);                   // 1
    count_deg_kernel<<<(E + 255) / 256, 256>>>(ei);               // 2
    gemm_bf16_kernel<1><<<ggrid, 256>>>(features, N);             // 3  T1 = X@W1 (ncu target)
    scan_phaseA<<<SCAN_BLOCKS, 1024>>>();                         // 4
    scan_phaseC<<<SCAN_BLOCKS, 1024>>>();                         // 5
    fill_kernel<<<(E + 255) / 256, 256>>>(ei);                    // 6
    aggBR_kernel<<<(N * 64 + 255) / 256, 256>>>(b1);              // 7  H1 = relu(agg(T1)+b1)
    gemm_bf16_kernel<2><<<ggrid, 256>>>(nullptr, N);              // 8  T2 = H1@W2
    aggBR_kernel<<<(N * 64 + 255) / 256, 256>>>(b2);              // 9  H2 = relu(agg(T2)+b2)
    gemm3_kernel<<<(N + 127) / 128, 256>>>(W3, N);                // 10 P = H2@W3
    aggout_kernel<<<(N * 32 + 255) / 256, 256>>>(b3, out, N);     // 11

    int NC = N * NCLS;
    if (out_size > NC) {
        int extra = out_size - NC;
        tail_kernel<<<(extra + 255) / 256, 256>>>(out, NC, out_size, (float)(3 * N));
    }
}